// round 9
// baseline (speedup 1.0000x reference)
#include <cuda_runtime.h>
#include <cuda_bf16.h>
#include <math.h>
#include <stdint.h>

// Problem constants
#define TOK     4096
#define DMODEL  1024
#define DHID    4096
#define NHEADS  16
#define DHEAD   64
#define SEQLEN  2048

typedef unsigned short ushort_t;

// ---------------- Scratch (allocation-free __device__ globals) -------------
__device__ ushort_t g_xh[TOK * DMODEL],  g_xl[TOK * DMODEL];
__device__ ushort_t g_Qh[TOK * DMODEL],  g_Ql[TOK * DMODEL];
__device__ ushort_t g_Kh[TOK * DMODEL],  g_Kl[TOK * DMODEL];
__device__ ushort_t g_Vh[TOK * DMODEL],  g_Vl[TOK * DMODEL];
__device__ ushort_t g_ctxh[TOK * DMODEL], g_ctxl[TOK * DMODEL];
__device__ ushort_t g_x1h[TOK * DMODEL], g_x1l[TOK * DMODEL];
__device__ ushort_t g_hh[TOK * DHID],    g_hl[TOK * DHID];
__device__ float g_x1[TOK * DMODEL];
__device__ float g_tmp[TOK * DMODEL];
__device__ ushort_t g_wqh[DMODEL * DMODEL], g_wql[DMODEL * DMODEL];
__device__ ushort_t g_wkh[DMODEL * DMODEL], g_wkl[DMODEL * DMODEL];
__device__ ushort_t g_wvh[DMODEL * DMODEL], g_wvl[DMODEL * DMODEL];
__device__ ushort_t g_woh[DMODEL * DMODEL], g_wol[DMODEL * DMODEL];
__device__ ushort_t g_w1h[DMODEL * DHID],   g_w1l[DMODEL * DHID];
__device__ ushort_t g_w2h[DHID * DMODEL],   g_w2l[DHID * DMODEL];

// ---------------------------------------------------------------------------
// Helpers
// ---------------------------------------------------------------------------
__device__ __forceinline__ uint32_t smem_u32(const void* p) {
    return (uint32_t)__cvta_generic_to_shared(p);
}
__device__ __forceinline__ void ldsm_x4(uint32_t* r, uint32_t a) {
    asm volatile("ldmatrix.sync.aligned.m8n8.x4.shared.b16 {%0,%1,%2,%3},[%4];\n"
                 : "=r"(r[0]), "=r"(r[1]), "=r"(r[2]), "=r"(r[3]) : "r"(a));
}
__device__ __forceinline__ void ldsm_x4t(uint32_t* r, uint32_t a) {
    asm volatile("ldmatrix.sync.aligned.m8n8.x4.trans.shared.b16 {%0,%1,%2,%3},[%4];\n"
                 : "=r"(r[0]), "=r"(r[1]), "=r"(r[2]), "=r"(r[3]) : "r"(a));
}
__device__ __forceinline__ void mma16816(float* d, const uint32_t* a, uint32_t b0, uint32_t b1) {
    asm volatile("mma.sync.aligned.m16n8k16.row.col.f32.bf16.bf16.f32 "
                 "{%0,%1,%2,%3},{%4,%5,%6,%7},{%8,%9},{%0,%1,%2,%3};\n"
                 : "+f"(d[0]), "+f"(d[1]), "+f"(d[2]), "+f"(d[3])
                 : "r"(a[0]), "r"(a[1]), "r"(a[2]), "r"(a[3]), "r"(b0), "r"(b1));
}
__device__ __forceinline__ void cp16(uint32_t dst, const void* src) {
    asm volatile("cp.async.cg.shared.global [%0], [%1], 16;\n" :: "r"(dst), "l"(src));
}
__device__ __forceinline__ void cp_commit() {
    asm volatile("cp.async.commit_group;\n");
}
template <int N>
__device__ __forceinline__ void cp_wait() {
    asm volatile("cp.async.wait_group %0;\n" :: "n"(N));
}
__device__ __forceinline__ void split2(float x, float y, uint32_t& hi, uint32_t& lo) {
    __nv_bfloat16 hx = __float2bfloat16(x), hy = __float2bfloat16(y);
    float rx = x - __bfloat162float(hx), ry = y - __bfloat162float(hy);
    __nv_bfloat16 lx = __float2bfloat16(rx), ly = __float2bfloat16(ry);
    hi = (uint32_t)__bfloat16_as_ushort(hx) | ((uint32_t)__bfloat16_as_ushort(hy) << 16);
    lo = (uint32_t)__bfloat16_as_ushort(lx) | ((uint32_t)__bfloat16_as_ushort(ly) << 16);
}

// ---------------------------------------------------------------------------
// Merged split kernel: 7 tensors in one launch. Segment table by value.
// ---------------------------------------------------------------------------
struct SplitArgs {
    const float4* in[7];
    uint2* hi[7];
    uint2* lo[7];
    int start[8];    // prefix sums of block counts
};

__global__ __launch_bounds__(256) void split_all_kernel(SplitArgs a)
{
    const int blk = blockIdx.x;
    int seg = 0;
#pragma unroll
    for (int i = 1; i < 7; i++) seg += (blk >= a.start[i]);
    const int idx = (blk - a.start[seg]) * 256 + threadIdx.x;

    float4 v = a.in[seg][idx];
    uint32_t h0, l0, h1, l1;
    split2(v.x, v.y, h0, l0);
    split2(v.z, v.w, h1, l1);
    a.hi[seg][idx] = make_uint2(h0, h1);
    a.lo[seg][idx] = make_uint2(l0, l1);
}

// ---------------------------------------------------------------------------
// Shared GEMM config (R4-proven: CTA 128x128, BK=32, 2-stage, 2 CTAs/SM)
// ---------------------------------------------------------------------------
#define APAD 40
#define BPAD 136
#define OFF_AH 0
#define OFF_AL (128 * APAD * 2)
#define OFF_BH (OFF_AL + 128 * APAD * 2)
#define OFF_BL (OFF_BH + 32 * BPAD * 2)
#define STAGE_BYTES (OFF_BL + 32 * BPAD * 2)   // 37888
#define GEMM_SMEM (2 * STAGE_BYTES)            // 75776

#define GEMM_PREAMBLE()                                                          \
    extern __shared__ char smem[];                                               \
    const uint32_t sbase = smem_u32(smem);                                       \
    const int t    = threadIdx.x;                                                \
    const int lane = t & 31;                                                     \
    const int warp = t >> 5;                                                     \
    const int wr   = warp >> 2;                                                  \
    const int wc   = warp & 3;                                                   \
    const int ar = t >> 2;                                                       \
    const int ac = (t & 3) << 3;                                                 \
    const int br = t >> 3;                                                       \
    const int bc = (t & 7) << 3;                                                 \
    const uint32_t dA0 = (uint32_t)(ar * APAD + ac) * 2;                         \
    const uint32_t dA1 = (uint32_t)((ar + 64) * APAD + ac) * 2;                  \
    const uint32_t dB0 = (uint32_t)(br * BPAD + bc) * 2;                         \
    const uint32_t dB1 = (uint32_t)(br * BPAD + bc + 64) * 2;                    \
    const int a_lm = (lane & 15) * APAD + (lane >> 4) * 8;                       \
    const int b_lm = (lane & 15) * BPAD + (lane >> 4) * 8;

#define LOAD_STAGE(s, k0)                                                        \
    do {                                                                         \
        const uint32_t sb = sbase + (s) * STAGE_BYTES;                           \
        cp16(sb + OFF_AH + dA0, Agh + (k0));                                     \
        cp16(sb + OFF_AH + dA1, Agh + (size_t)64 * K + (k0));                    \
        cp16(sb + OFF_AL + dA0, Agl + (k0));                                     \
        cp16(sb + OFF_AL + dA1, Agl + (size_t)64 * K + (k0));                    \
        cp16(sb + OFF_BH + dB0, Wgh + (size_t)(k0) * N);                         \
        cp16(sb + OFF_BH + dB1, Wgh + (size_t)(k0) * N + 64);                    \
        cp16(sb + OFF_BL + dB0, Wgl + (size_t)(k0) * N);                         \
        cp16(sb + OFF_BL + dB1, Wgl + (size_t)(k0) * N + 64);                    \
    } while (0)

#define GEMM_MAINLOOP()                                                          \
    float acc[4][4][4];                                                          \
    _Pragma("unroll")                                                            \
    for (int i = 0; i < 4; i++)                                                  \
        _Pragma("unroll")                                                        \
        for (int j = 0; j < 4; j++)                                              \
            _Pragma("unroll")                                                    \
            for (int q = 0; q < 4; q++) acc[i][j][q] = 0.f;                      \
    const int ntiles = K >> 5;                                                   \
    LOAD_STAGE(0, 0);                                                            \
    cp_commit();                                                                 \
    for (int kt = 0; kt < ntiles; kt++) {                                        \
        if (kt + 1 < ntiles) LOAD_STAGE((kt + 1) & 1, (kt + 1) << 5);            \
        cp_commit();                                                             \
        cp_wait<1>();                                                            \
        __syncthreads();                                                         \
        const uint32_t sb = sbase + (kt & 1) * STAGE_BYTES;                      \
        _Pragma("unroll")                                                        \
        for (int ks = 0; ks < 2; ks++) {                                         \
            uint32_t ah[4][4], al[4][4];                                         \
            _Pragma("unroll")                                                    \
            for (int mt = 0; mt < 4; mt++) {                                     \
                const uint32_t base = sb + 2 * ((wr * 64 + mt * 16) * APAD + ks * 16 + a_lm); \
                ldsm_x4(ah[mt], base + OFF_AH);                                  \
                ldsm_x4(al[mt], base + OFF_AL);                                  \
            }                                                                    \
            _Pragma("unroll")                                                    \
            for (int np = 0; np < 2; np++) {                                     \
                uint32_t bh[4], bl[4];                                           \
                const uint32_t base = sb + 2 * ((ks * 16) * BPAD + wc * 32 + np * 16 + b_lm); \
                ldsm_x4t(bh, base + OFF_BH);                                     \
                ldsm_x4t(bl, base + OFF_BL);                                     \
                _Pragma("unroll")                                                \
                for (int mt = 0; mt < 4; mt++) {                                 \
                    mma16816(acc[mt][np * 2 + 0], ah[mt], bh[0], bh[1]);         \
                    mma16816(acc[mt][np * 2 + 0], ah[mt], bl[0], bl[1]);         \
                    mma16816(acc[mt][np * 2 + 0], al[mt], bh[0], bh[1]);         \
                    mma16816(acc[mt][np * 2 + 1], ah[mt], bh[2], bh[3]);         \
                    mma16816(acc[mt][np * 2 + 1], ah[mt], bl[2], bl[3]);         \
                    mma16816(acc[mt][np * 2 + 1], al[mt], bh[2], bh[3]);         \
                }                                                                \
            }                                                                    \
        }                                                                        \
        __syncthreads();                                                         \
    }

// ---------------------------------------------------------------------------
// Generic GEMM (EPI: 0 none | 2 +bias,gelu ; OUT: 0 fp32 | 1 split)
// ---------------------------------------------------------------------------
template <int EPI, int OUT>
__global__ __launch_bounds__(256) void gemm_pipe(
    const ushort_t* __restrict__ Ah, const ushort_t* __restrict__ Al,
    const ushort_t* __restrict__ Wh, const ushort_t* __restrict__ Wl,
    const float* __restrict__ bias,
    float* __restrict__ Cf, ushort_t* __restrict__ Ch, ushort_t* __restrict__ Cl,
    int M, int K, int N)
{
    GEMM_PREAMBLE()
    const int rowBase = blockIdx.y * 128;
    const int colBase = blockIdx.x * 128;

    const ushort_t* Agh = Ah + (size_t)(rowBase + ar) * K + ac;
    const ushort_t* Agl = Al + (size_t)(rowBase + ar) * K + ac;
    const ushort_t* Wgh = Wh + (size_t)br * N + colBase + bc;
    const ushort_t* Wgl = Wl + (size_t)br * N + colBase + bc;

    GEMM_MAINLOOP()

    const int g  = lane >> 2;
    const int tq = lane & 3;
    const int rB = rowBase + wr * 64;
    const int cB = colBase + wc * 32;

#pragma unroll
    for (int mt = 0; mt < 4; mt++) {
#pragma unroll
        for (int nt = 0; nt < 4; nt++) {
            const int row = rB + mt * 16 + g;
            const int col = cB + nt * 8 + tq * 2;
            float b0 = 0.f, b1 = 0.f;
            if (EPI >= 1) { b0 = bias[col]; b1 = bias[col + 1]; }
            float v0 = acc[mt][nt][0] + b0;
            float v1 = acc[mt][nt][1] + b1;
            float v2 = acc[mt][nt][2] + b0;
            float v3 = acc[mt][nt][3] + b1;
            if (EPI == 2) {
                v0 = 0.5f * v0 * (1.0f + erff(v0 * 0.7071067811865475f));
                v1 = 0.5f * v1 * (1.0f + erff(v1 * 0.7071067811865475f));
                v2 = 0.5f * v2 * (1.0f + erff(v2 * 0.7071067811865475f));
                v3 = 0.5f * v3 * (1.0f + erff(v3 * 0.7071067811865475f));
            }
            if (OUT == 0) {
                *(float2*)&Cf[(size_t)row * N + col]       = make_float2(v0, v1);
                *(float2*)&Cf[(size_t)(row + 8) * N + col] = make_float2(v2, v3);
            } else {
                uint32_t ph, pl;
                split2(v0, v1, ph, pl);
                *(uint32_t*)&Ch[(size_t)row * N + col] = ph;
                *(uint32_t*)&Cl[(size_t)row * N + col] = pl;
                split2(v2, v3, ph, pl);
                *(uint32_t*)&Ch[(size_t)(row + 8) * N + col] = ph;
                *(uint32_t*)&Cl[(size_t)(row + 8) * N + col] = pl;
            }
        }
    }
}

// ---------------------------------------------------------------------------
// Fused QKV GEMM: one launch, grid (24, 32). blockIdx.x>>3 selects Q/K/V.
// ---------------------------------------------------------------------------
__global__ __launch_bounds__(256) void gemm_qkv(
    const ushort_t* __restrict__ Ah, const ushort_t* __restrict__ Al,
    const ushort_t* __restrict__ Wqh, const ushort_t* __restrict__ Wql,
    const ushort_t* __restrict__ Wkh, const ushort_t* __restrict__ Wkl,
    const ushort_t* __restrict__ Wvh, const ushort_t* __restrict__ Wvl,
    const float* __restrict__ bq, const float* __restrict__ bk, const float* __restrict__ bv,
    ushort_t* __restrict__ Qh, ushort_t* __restrict__ Ql,
    ushort_t* __restrict__ Kh, ushort_t* __restrict__ Kl,
    ushort_t* __restrict__ Vh, ushort_t* __restrict__ Vl)
{
    GEMM_PREAMBLE()
    const int K = DMODEL, N = DMODEL;
    const int sel = blockIdx.x >> 3;
    const int rowBase = blockIdx.y * 128;
    const int colBase = (blockIdx.x & 7) * 128;

    const ushort_t* Wh = (sel == 0) ? Wqh : (sel == 1) ? Wkh : Wvh;
    const ushort_t* Wl = (sel == 0) ? Wql : (sel == 1) ? Wkl : Wvl;
    const float* bias  = (sel == 0) ? bq  : (sel == 1) ? bk  : bv;
    ushort_t* Ch       = (sel == 0) ? Qh  : (sel == 1) ? Kh  : Vh;
    ushort_t* Cl       = (sel == 0) ? Ql  : (sel == 1) ? Kl  : Vl;
    const float scale  = (sel == 0) ? 0.125f : 1.0f;

    const ushort_t* Agh = Ah + (size_t)(rowBase + ar) * K + ac;
    const ushort_t* Agl = Al + (size_t)(rowBase + ar) * K + ac;
    const ushort_t* Wgh = Wh + (size_t)br * N + colBase + bc;
    const ushort_t* Wgl = Wl + (size_t)br * N + colBase + bc;

    GEMM_MAINLOOP()

    const int g  = lane >> 2;
    const int tq = lane & 3;
    const int rB = rowBase + wr * 64;
    const int cB = colBase + wc * 32;

#pragma unroll
    for (int mt = 0; mt < 4; mt++) {
#pragma unroll
        for (int nt = 0; nt < 4; nt++) {
            const int row = rB + mt * 16 + g;
            const int col = cB + nt * 8 + tq * 2;
            const float b0 = bias[col], b1 = bias[col + 1];
            float v0 = (acc[mt][nt][0] + b0) * scale;
            float v1 = (acc[mt][nt][1] + b1) * scale;
            float v2 = (acc[mt][nt][2] + b0) * scale;
            float v3 = (acc[mt][nt][3] + b1) * scale;
            uint32_t ph, pl;
            split2(v0, v1, ph, pl);
            *(uint32_t*)&Ch[(size_t)row * N + col] = ph;
            *(uint32_t*)&Cl[(size_t)row * N + col] = pl;
            split2(v2, v3, ph, pl);
            *(uint32_t*)&Ch[(size_t)(row + 8) * N + col] = ph;
            *(uint32_t*)&Cl[(size_t)(row + 8) * N + col] = pl;
        }
    }
}

// ---------------------------------------------------------------------------
// Tensor-core causal flash attention, cp.async double-buffered K/V.
// Grid: (S/64, H, B). Block 128 = 4 warps x 16 query rows.
// Dynamic smem: 2 bufs x {Kh,Kl,Vh,Vl} x 64 x KPAD bf16 = 73728 B -> 3 CTAs/SM
// (same as register-limited occupancy of single-buffer version).
// ---------------------------------------------------------------------------
#define KPAD 72
#define AT_ARR  (64 * KPAD * 2)     // 9216 B per array
#define AT_BUF  (4 * AT_ARR)        // 36864 B per buffer
#define ATT_SMEM (2 * AT_BUF)       // 73728 B

__global__ __launch_bounds__(128) void attn_tc_kernel(
    const ushort_t* __restrict__ Qh, const ushort_t* __restrict__ Ql,
    const ushort_t* __restrict__ Kh, const ushort_t* __restrict__ Kl,
    const ushort_t* __restrict__ Vh, const ushort_t* __restrict__ Vl,
    ushort_t* __restrict__ Oh, ushort_t* __restrict__ Ol)
{
    extern __shared__ char smem[];
    const uint32_t sb = smem_u32(smem);

    const int qb = blockIdx.x;
    const int h  = blockIdx.y;
    const int b  = blockIdx.z;
    const int t  = threadIdx.x;
    const int lane = t & 31;
    const int warp = t >> 5;
    const int q0 = qb << 6;

    const int g  = lane >> 2;
    const int tq = lane & 3;

    const int lr = t >> 1;
    const int lc = (t & 1) << 5;
    const int lm = (lane & 15) * KPAD + (lane >> 4) * 8;

    // ---- Stage Q into buf0 K-arrays, preload fragments ----
    {
        const size_t gb = (size_t)(b * SEQLEN + q0 + lr) * DMODEL + h * DHEAD + lc;
        char* s0 = smem;
#pragma unroll
        for (int u = 0; u < 4; u++) {
            *(uint4*)(s0 + 0      + (lr * KPAD + lc + u * 8) * 2) = *(const uint4*)(Qh + gb + u * 8);
            *(uint4*)(s0 + AT_ARR + (lr * KPAD + lc + u * 8) * 2) = *(const uint4*)(Ql + gb + u * 8);
        }
    }
    __syncthreads();

    uint32_t qfh[4][4], qfl[4][4];
#pragma unroll
    for (int kc = 0; kc < 4; kc++) {
        const uint32_t base = sb + 2 * ((warp * 16) * KPAD + kc * 16 + lm);
        ldsm_x4(qfh[kc], base);
        ldsm_x4(qfl[kc], base + AT_ARR);
    }
    __syncthreads();

    // ---- K/V async loader ----
    auto load_kv = [&](int buf, int j0) {
        const uint32_t bb = sb + buf * AT_BUF;
        const size_t gb = (size_t)(b * SEQLEN + j0 + lr) * DMODEL + h * DHEAD + lc;
#pragma unroll
        for (int u = 0; u < 4; u++) {
            const uint32_t d = (uint32_t)(lr * KPAD + lc + u * 8) * 2;
            cp16(bb + 0 * AT_ARR + d, Kh + gb + u * 8);
            cp16(bb + 1 * AT_ARR + d, Kl + gb + u * 8);
            cp16(bb + 2 * AT_ARR + d, Vh + gb + u * 8);
            cp16(bb + 3 * AT_ARR + d, Vl + gb + u * 8);
        }
    };

    float m0 = -1e30f, m1 = -1e30f, l0 = 0.f, l1 = 0.f;
    float o[8][4];
#pragma unroll
    for (int j = 0; j < 8; j++)
#pragma unroll
        for (int q = 0; q < 4; q++) o[j][q] = 0.f;

    load_kv(0, 0);
    cp_commit();

    for (int jb = 0; jb <= qb; jb++) {
        if (jb < qb) { load_kv((jb + 1) & 1, (jb + 1) << 6); cp_commit(); cp_wait<1>(); }
        else         { cp_wait<0>(); }
        __syncthreads();

        const uint32_t bb = sb + (jb & 1) * AT_BUF;

        // S = Q K^T
        float s[8][4];
#pragma unroll
        for (int j = 0; j < 8; j++)
#pragma unroll
            for (int q = 0; q < 4; q++) s[j][q] = 0.f;

#pragma unroll
        for (int kc = 0; kc < 4; kc++) {
#pragma unroll
            for (int kt = 0; kt < 4; kt++) {
                uint32_t kbh[4], kbl[4];
                const uint32_t base = bb + 2 * ((kt * 16) * KPAD + kc * 16 + lm);
                ldsm_x4(kbh, base);
                ldsm_x4(kbl, base + AT_ARR);
                mma16816(s[kt * 2 + 0], qfh[kc], kbh[0], kbh[2]);
                mma16816(s[kt * 2 + 0], qfh[kc], kbl[0], kbl[2]);
                mma16816(s[kt * 2 + 0], qfl[kc], kbh[0], kbh[2]);
                mma16816(s[kt * 2 + 1], qfh[kc], kbh[1], kbh[3]);
                mma16816(s[kt * 2 + 1], qfh[kc], kbl[1], kbl[3]);
                mma16816(s[kt * 2 + 1], qfl[kc], kbh[1], kbh[3]);
            }
        }

        if (jb == qb) {
            const int r0 = warp * 16 + g;
            const int r1 = r0 + 8;
#pragma unroll
            for (int j = 0; j < 8; j++) {
                const int c0 = j * 8 + tq * 2;
                if (c0 > r0)     s[j][0] = -1e30f;
                if (c0 + 1 > r0) s[j][1] = -1e30f;
                if (c0 > r1)     s[j][2] = -1e30f;
                if (c0 + 1 > r1) s[j][3] = -1e30f;
            }
        }

        float rm0 = -1e30f, rm1 = -1e30f;
#pragma unroll
        for (int j = 0; j < 8; j++) {
            rm0 = fmaxf(rm0, fmaxf(s[j][0], s[j][1]));
            rm1 = fmaxf(rm1, fmaxf(s[j][2], s[j][3]));
        }
        rm0 = fmaxf(rm0, __shfl_xor_sync(0xffffffffu, rm0, 1));
        rm0 = fmaxf(rm0, __shfl_xor_sync(0xffffffffu, rm0, 2));
        rm1 = fmaxf(rm1, __shfl_xor_sync(0xffffffffu, rm1, 1));
        rm1 = fmaxf(rm1, __shfl_xor_sync(0xffffffffu, rm1, 2));
        const float nm0 = fmaxf(m0, rm0);
        const float nm1 = fmaxf(m1, rm1);

        float rs0 = 0.f, rs1 = 0.f;
#pragma unroll
        for (int j = 0; j < 8; j++) {
            s[j][0] = __expf(s[j][0] - nm0);
            s[j][1] = __expf(s[j][1] - nm0);
            s[j][2] = __expf(s[j][2] - nm1);
            s[j][3] = __expf(s[j][3] - nm1);
            rs0 += s[j][0] + s[j][1];
            rs1 += s[j][2] + s[j][3];
        }
        rs0 += __shfl_xor_sync(0xffffffffu, rs0, 1);
        rs0 += __shfl_xor_sync(0xffffffffu, rs0, 2);
        rs1 += __shfl_xor_sync(0xffffffffu, rs1, 1);
        rs1 += __shfl_xor_sync(0xffffffffu, rs1, 2);

        const float sc0 = __expf(m0 - nm0);
        const float sc1 = __expf(m1 - nm1);
        l0 = l0 * sc0 + rs0;  m0 = nm0;
        l1 = l1 * sc1 + rs1;  m1 = nm1;
#pragma unroll
        for (int j = 0; j < 8; j++) {
            o[j][0] *= sc0; o[j][1] *= sc0;
            o[j][2] *= sc1; o[j][3] *= sc1;
        }

        // O += P V
#pragma unroll
        for (int kc = 0; kc < 4; kc++) {
            uint32_t pah[4], pal[4];
            split2(s[2 * kc + 0][0], s[2 * kc + 0][1], pah[0], pal[0]);
            split2(s[2 * kc + 0][2], s[2 * kc + 0][3], pah[1], pal[1]);
            split2(s[2 * kc + 1][0], s[2 * kc + 1][1], pah[2], pal[2]);
            split2(s[2 * kc + 1][2], s[2 * kc + 1][3], pah[3], pal[3]);
#pragma unroll
            for (int dt = 0; dt < 4; dt++) {
                uint32_t vbh[4], vbl[4];
                const uint32_t base = bb + 2 * AT_ARR + 2 * ((kc * 16) * KPAD + dt * 16 + lm);
                ldsm_x4t(vbh, base);
                ldsm_x4t(vbl, base + AT_ARR);
                mma16816(o[dt * 2 + 0], pah, vbh[0], vbh[1]);
                mma16816(o[dt * 2 + 0], pah, vbl[0], vbl[1]);
                mma16816(o[dt * 2 + 0], pal, vbh[0], vbh[1]);
                mma16816(o[dt * 2 + 1], pah, vbh[2], vbh[3]);
                mma16816(o[dt * 2 + 1], pah, vbl[2], vbl[3]);
                mma16816(o[dt * 2 + 1], pal, vbh[2], vbh[3]);
            }
        }
        __syncthreads();
    }

    const float inv0 = 1.0f / l0;
    const float inv1 = 1.0f / l1;
    const int row0 = q0 + warp * 16 + g;
#pragma unroll
    for (int j = 0; j < 8; j++) {
        const int col = h * DHEAD + j * 8 + tq * 2;
        uint32_t phh, pll;
        split2(o[j][0] * inv0, o[j][1] * inv0, phh, pll);
        *(uint32_t*)&Oh[(size_t)(b * SEQLEN + row0) * DMODEL + col] = phh;
        *(uint32_t*)&Ol[(size_t)(b * SEQLEN + row0) * DMODEL + col] = pll;
        split2(o[j][2] * inv1, o[j][3] * inv1, phh, pll);
        *(uint32_t*)&Oh[(size_t)(b * SEQLEN + row0 + 8) * DMODEL + col] = phh;
        *(uint32_t*)&Ol[(size_t)(b * SEQLEN + row0 + 8) * DMODEL + col] = pll;
    }
}

// ---------------------------------------------------------------------------
// LN: one block per row, float4 per thread, warp-shuffle reduction.
// ---------------------------------------------------------------------------
template <bool SPLIT>
__global__ __launch_bounds__(256) void ln_res_kernel(
    const float* __restrict__ xres, const float* __restrict__ tin,
    const float* __restrict__ gam, const float* __restrict__ bet,
    float* __restrict__ out, ushort_t* __restrict__ outh, ushort_t* __restrict__ outl)
{
    const int row = blockIdx.x;
    const int tid = threadIdx.x;
    const int lane = tid & 31;
    const int warp = tid >> 5;

    const float4 v = ((const float4*)(tin + (size_t)row * DMODEL))[tid];

    float sum = v.x + v.y + v.z + v.w;
    float sq  = v.x * v.x + v.y * v.y + v.z * v.z + v.w * v.w;
#pragma unroll
    for (int off = 16; off; off >>= 1) {
        sum += __shfl_xor_sync(0xffffffffu, sum, off);
        sq  += __shfl_xor_sync(0xffffffffu, sq,  off);
    }

    __shared__ float sS[8], sQ[8];
    __shared__ float s_mu, s_rstd;
    if (lane == 0) { sS[warp] = sum; sQ[warp] = sq; }
    __syncthreads();
    if (tid == 0) {
        float ts = 0.f, tq2 = 0.f;
#pragma unroll
        for (int w = 0; w < 8; w++) { ts += sS[w]; tq2 += sQ[w]; }
        const float mu  = ts * (1.0f / DMODEL);
        const float var = tq2 * (1.0f / DMODEL) - mu * mu;
        s_mu = mu;
        s_rstd = rsqrtf(var + 1e-5f);
    }
    __syncthreads();

    const float mu = s_mu, rstd = s_rstd;
    const float4 xr = ((const float4*)(xres + (size_t)row * DMODEL))[tid];
    const float4 gm = ((const float4*)gam)[tid];
    const float4 bt = ((const float4*)bet)[tid];

    float4 ov;
    ov.x = xr.x + (v.x - mu) * rstd * gm.x + bt.x;
    ov.y = xr.y + (v.y - mu) * rstd * gm.y + bt.y;
    ov.z = xr.z + (v.z - mu) * rstd * gm.z + bt.z;
    ov.w = xr.w + (v.w - mu) * rstd * gm.w + bt.w;

    ((float4*)(out + (size_t)row * DMODEL))[tid] = ov;
    if (SPLIT) {
        uint32_t h0, l0, h1, l1;
        split2(ov.x, ov.y, h0, l0);
        split2(ov.z, ov.w, h1, l1);
        ((uint2*)outh)[(size_t)row * 256 + tid] = make_uint2(h0, h1);
        ((uint2*)outl)[(size_t)row * 256 + tid] = make_uint2(l0, l1);
    }
}

// ---------------------------------------------------------------------------
extern "C" void kernel_launch(void* const* d_in, const int* in_sizes, int n_in,
                              void* d_out, int out_size)
{
    const float* x    = (const float*)d_in[0];
    const float* wq   = (const float*)d_in[1];
    const float* bq   = (const float*)d_in[2];
    const float* wk   = (const float*)d_in[3];
    const float* bk   = (const float*)d_in[4];
    const float* wv   = (const float*)d_in[5];
    const float* bv   = (const float*)d_in[6];
    const float* wo   = (const float*)d_in[7];
    const float* ln1g = (const float*)d_in[8];
    const float* ln1b = (const float*)d_in[9];
    const float* w1   = (const float*)d_in[10];
    const float* b1   = (const float*)d_in[11];
    const float* w2   = (const float*)d_in[12];
    const float* ln2g = (const float*)d_in[13];
    const float* ln2b = (const float*)d_in[14];
    float* out = (float*)d_out;

#define SYM(T, name, sym) T* name; { void* p_; cudaGetSymbolAddress(&p_, sym); name = (T*)p_; }
    SYM(ushort_t, xh, g_xh)   SYM(ushort_t, xl, g_xl)
    SYM(ushort_t, Qh, g_Qh)   SYM(ushort_t, Ql, g_Ql)
    SYM(ushort_t, Kh, g_Kh)   SYM(ushort_t, Kl, g_Kl)
    SYM(ushort_t, Vh, g_Vh)   SYM(ushort_t, Vl, g_Vl)
    SYM(ushort_t, ctxh, g_ctxh) SYM(ushort_t, ctxl, g_ctxl)
    SYM(ushort_t, x1h, g_x1h) SYM(ushort_t, x1l, g_x1l)
    SYM(ushort_t, hh, g_hh)   SYM(ushort_t, hl, g_hl)
    SYM(float, x1f, g_x1)     SYM(float, tmp, g_tmp)
    SYM(ushort_t, wqh, g_wqh) SYM(ushort_t, wql, g_wql)
    SYM(ushort_t, wkh, g_wkh) SYM(ushort_t, wkl, g_wkl)
    SYM(ushort_t, wvh, g_wvh) SYM(ushort_t, wvl, g_wvl)
    SYM(ushort_t, woh, g_woh) SYM(ushort_t, wol, g_wol)
    SYM(ushort_t, w1h, g_w1h) SYM(ushort_t, w1l, g_w1l)
    SYM(ushort_t, w2h, g_w2h) SYM(ushort_t, w2l, g_w2l)
#undef SYM

    static bool attr_done = false;
    if (!attr_done) {
        cudaFuncSetAttribute(gemm_pipe<0, 0>, cudaFuncAttributeMaxDynamicSharedMemorySize, GEMM_SMEM);
        cudaFuncSetAttribute(gemm_pipe<2, 1>, cudaFuncAttributeMaxDynamicSharedMemorySize, GEMM_SMEM);
        cudaFuncSetAttribute(gemm_qkv,        cudaFuncAttributeMaxDynamicSharedMemorySize, GEMM_SMEM);
        cudaFuncSetAttribute(attn_tc_kernel,  cudaFuncAttributeMaxDynamicSharedMemorySize, ATT_SMEM);
        attr_done = true;
    }

    // 0) one-time splits: single merged launch (7 segments)
    {
        SplitArgs a;
        const float4* ins[7] = {(const float4*)x, (const float4*)wq, (const float4*)wk,
                                (const float4*)wv, (const float4*)wo, (const float4*)w1,
                                (const float4*)w2};
        uint2* his[7] = {(uint2*)xh, (uint2*)wqh, (uint2*)wkh, (uint2*)wvh,
                         (uint2*)woh, (uint2*)w1h, (uint2*)w2h};
        uint2* los[7] = {(uint2*)xl, (uint2*)wql, (uint2*)wkl, (uint2*)wvl,
                         (uint2*)wol, (uint2*)w1l, (uint2*)w2l};
        const int nblk[7] = {TOK * DMODEL / 1024, DMODEL * DMODEL / 1024,
                             DMODEL * DMODEL / 1024, DMODEL * DMODEL / 1024,
                             DMODEL * DMODEL / 1024, DMODEL * DHID / 1024,
                             DHID * DMODEL / 1024};
        int acc = 0;
        for (int i = 0; i < 7; i++) {
            a.in[i] = ins[i]; a.hi[i] = his[i]; a.lo[i] = los[i];
            a.start[i] = acc; acc += nblk[i];
        }
        a.start[7] = acc;
        split_all_kernel<<<acc, 256>>>(a);
    }

    // 1) fused QKV projection (Q pre-scaled by 1/8)
    gemm_qkv<<<dim3(24, 32), 256, GEMM_SMEM>>>(
        xh, xl, wqh, wql, wkh, wkl, wvh, wvl, bq, bk, bv,
        Qh, Ql, Kh, Kl, Vh, Vl);

    // 2) attention (double-buffered K/V)
    attn_tc_kernel<<<dim3(SEQLEN / 64, NHEADS, 2), 128, ATT_SMEM>>>(Qh, Ql, Kh, Kl, Vh, Vl, ctxh, ctxl);

    // 3) Wo projection -> tmp (fp32)
    gemm_pipe<0, 0><<<dim3(8, 32), 256, GEMM_SMEM>>>(ctxh, ctxl, woh, wol, nullptr, tmp, nullptr, nullptr, TOK, DMODEL, DMODEL);

    // 4) x1 = x + LN1(tmp), also split
    ln_res_kernel<true><<<TOK, 256>>>(x, tmp, ln1g, ln1b, x1f, x1h, x1l);

    // 5) h = gelu(x1 @ w1 + b1), split out
    gemm_pipe<2, 1><<<dim3(32, 32), 256, GEMM_SMEM>>>(x1h, x1l, w1h, w1l, b1, nullptr, hh, hl, TOK, DMODEL, DHID);

    // 6) tmp = h @ w2
    gemm_pipe<0, 0><<<dim3(8, 32), 256, GEMM_SMEM>>>(hh, hl, w2h, w2l, nullptr, tmp, nullptr, nullptr, TOK, DHID, DMODEL);

    // 7) out = x1 + LN2(tmp)
    ln_res_kernel<false><<<TOK, 256>>>(x1f, tmp, ln2g, ln2b, out, nullptr, nullptr);
}

// round 10
// speedup vs baseline: 1.0493x; 1.0493x over previous
#include <cuda_runtime.h>
#include <cuda_bf16.h>
#include <math.h>
#include <stdint.h>

// Problem constants
#define TOK     4096
#define DMODEL  1024
#define DHID    4096
#define NHEADS  16
#define DHEAD   64
#define SEQLEN  2048

typedef unsigned short ushort_t;

// ---------------- Scratch (allocation-free __device__ globals) -------------
__device__ ushort_t g_xh[TOK * DMODEL],  g_xl[TOK * DMODEL];
__device__ ushort_t g_Qh[TOK * DMODEL],  g_Ql[TOK * DMODEL];
__device__ ushort_t g_Kh[TOK * DMODEL],  g_Kl[TOK * DMODEL];
__device__ ushort_t g_Vh[TOK * DMODEL],  g_Vl[TOK * DMODEL];
__device__ ushort_t g_ctxh[TOK * DMODEL], g_ctxl[TOK * DMODEL];
__device__ ushort_t g_x1h[TOK * DMODEL], g_x1l[TOK * DMODEL];
__device__ ushort_t g_hh[TOK * DHID],    g_hl[TOK * DHID];
__device__ float g_x1[TOK * DMODEL];
__device__ float g_tmp[TOK * DMODEL];
__device__ ushort_t g_wqh[DMODEL * DMODEL], g_wql[DMODEL * DMODEL];
__device__ ushort_t g_wkh[DMODEL * DMODEL], g_wkl[DMODEL * DMODEL];
__device__ ushort_t g_wvh[DMODEL * DMODEL], g_wvl[DMODEL * DMODEL];
__device__ ushort_t g_woh[DMODEL * DMODEL], g_wol[DMODEL * DMODEL];
__device__ ushort_t g_w1h[DMODEL * DHID],   g_w1l[DMODEL * DHID];
__device__ ushort_t g_w2h[DHID * DMODEL],   g_w2l[DHID * DMODEL];

// ---------------------------------------------------------------------------
// Helpers
// ---------------------------------------------------------------------------
__device__ __forceinline__ uint32_t smem_u32(const void* p) {
    return (uint32_t)__cvta_generic_to_shared(p);
}
__device__ __forceinline__ void ldsm_x4(uint32_t* r, uint32_t a) {
    asm volatile("ldmatrix.sync.aligned.m8n8.x4.shared.b16 {%0,%1,%2,%3},[%4];\n"
                 : "=r"(r[0]), "=r"(r[1]), "=r"(r[2]), "=r"(r[3]) : "r"(a));
}
__device__ __forceinline__ void ldsm_x4t(uint32_t* r, uint32_t a) {
    asm volatile("ldmatrix.sync.aligned.m8n8.x4.trans.shared.b16 {%0,%1,%2,%3},[%4];\n"
                 : "=r"(r[0]), "=r"(r[1]), "=r"(r[2]), "=r"(r[3]) : "r"(a));
}
__device__ __forceinline__ void mma16816(float* d, const uint32_t* a, uint32_t b0, uint32_t b1) {
    asm volatile("mma.sync.aligned.m16n8k16.row.col.f32.bf16.bf16.f32 "
                 "{%0,%1,%2,%3},{%4,%5,%6,%7},{%8,%9},{%0,%1,%2,%3};\n"
                 : "+f"(d[0]), "+f"(d[1]), "+f"(d[2]), "+f"(d[3])
                 : "r"(a[0]), "r"(a[1]), "r"(a[2]), "r"(a[3]), "r"(b0), "r"(b1));
}
__device__ __forceinline__ void cp16(uint32_t dst, const void* src) {
    asm volatile("cp.async.ca.shared.global [%0], [%1], 16;\n" :: "r"(dst), "l"(src));
}
__device__ __forceinline__ void cp_commit() {
    asm volatile("cp.async.commit_group;\n");
}
template <int N>
__device__ __forceinline__ void cp_wait() {
    asm volatile("cp.async.wait_group %0;\n" :: "n"(N));
}
__device__ __forceinline__ void split2(float x, float y, uint32_t& hi, uint32_t& lo) {
    __nv_bfloat16 hx = __float2bfloat16(x), hy = __float2bfloat16(y);
    float rx = x - __bfloat162float(hx), ry = y - __bfloat162float(hy);
    __nv_bfloat16 lx = __float2bfloat16(rx), ly = __float2bfloat16(ry);
    hi = (uint32_t)__bfloat16_as_ushort(hx) | ((uint32_t)__bfloat16_as_ushort(hy) << 16);
    lo = (uint32_t)__bfloat16_as_ushort(lx) | ((uint32_t)__bfloat16_as_ushort(ly) << 16);
}

// ---------------------------------------------------------------------------
// Merged split kernel: 7 tensors in one launch. Segment table by value.
// ---------------------------------------------------------------------------
struct SplitArgs {
    const float4* in[7];
    uint2* hi[7];
    uint2* lo[7];
    int start[8];    // prefix sums of block counts
};

__global__ __launch_bounds__(256) void split_all_kernel(SplitArgs a)
{
    const int blk = blockIdx.x;
    int seg = 0;
#pragma unroll
    for (int i = 1; i < 7; i++) seg += (blk >= a.start[i]);
    const int idx = (blk - a.start[seg]) * 256 + threadIdx.x;

    float4 v = a.in[seg][idx];
    uint32_t h0, l0, h1, l1;
    split2(v.x, v.y, h0, l0);
    split2(v.z, v.w, h1, l1);
    a.hi[seg][idx] = make_uint2(h0, h1);
    a.lo[seg][idx] = make_uint2(l0, l1);
}

// ---------------------------------------------------------------------------
// Shared GEMM config (R4-proven: CTA 128x128, BK=32, 2-stage, 2 CTAs/SM)
// ---------------------------------------------------------------------------
#define APAD 40
#define BPAD 136
#define OFF_AH 0
#define OFF_AL (128 * APAD * 2)
#define OFF_BH (OFF_AL + 128 * APAD * 2)
#define OFF_BL (OFF_BH + 32 * BPAD * 2)
#define STAGE_BYTES (OFF_BL + 32 * BPAD * 2)   // 37888
#define GEMM_SMEM (2 * STAGE_BYTES)            // 75776

#define GEMM_PREAMBLE()                                                          \
    extern __shared__ char smem[];                                               \
    const uint32_t sbase = smem_u32(smem);                                       \
    const int t    = threadIdx.x;                                                \
    const int lane = t & 31;                                                     \
    const int warp = t >> 5;                                                     \
    const int wr   = warp >> 2;                                                  \
    const int wc   = warp & 3;                                                   \
    const int ar = t >> 2;                                                       \
    const int ac = (t & 3) << 3;                                                 \
    const int br = t >> 3;                                                       \
    const int bc = (t & 7) << 3;                                                 \
    const uint32_t dA0 = (uint32_t)(ar * APAD + ac) * 2;                         \
    const uint32_t dA1 = (uint32_t)((ar + 64) * APAD + ac) * 2;                  \
    const uint32_t dB0 = (uint32_t)(br * BPAD + bc) * 2;                         \
    const uint32_t dB1 = (uint32_t)(br * BPAD + bc + 64) * 2;                    \
    const int a_lm = (lane & 15) * APAD + (lane >> 4) * 8;                       \
    const int b_lm = (lane & 15) * BPAD + (lane >> 4) * 8;

#define LOAD_STAGE(s, k0)                                                        \
    do {                                                                         \
        const uint32_t sb = sbase + (s) * STAGE_BYTES;                           \
        cp16(sb + OFF_AH + dA0, Agh + (k0));                                     \
        cp16(sb + OFF_AH + dA1, Agh + (size_t)64 * K + (k0));                    \
        cp16(sb + OFF_AL + dA0, Agl + (k0));                                     \
        cp16(sb + OFF_AL + dA1, Agl + (size_t)64 * K + (k0));                    \
        cp16(sb + OFF_BH + dB0, Wgh + (size_t)(k0) * N);                         \
        cp16(sb + OFF_BH + dB1, Wgh + (size_t)(k0) * N + 64);                    \
        cp16(sb + OFF_BL + dB0, Wgl + (size_t)(k0) * N);                         \
        cp16(sb + OFF_BL + dB1, Wgl + (size_t)(k0) * N + 64);                    \
    } while (0)

#define GEMM_MAINLOOP()                                                          \
    float acc[4][4][4];                                                          \
    _Pragma("unroll")                                                            \
    for (int i = 0; i < 4; i++)                                                  \
        _Pragma("unroll")                                                        \
        for (int j = 0; j < 4; j++)                                              \
            _Pragma("unroll")                                                    \
            for (int q = 0; q < 4; q++) acc[i][j][q] = 0.f;                      \
    const int ntiles = K >> 5;                                                   \
    LOAD_STAGE(0, 0);                                                            \
    cp_commit();                                                                 \
    for (int kt = 0; kt < ntiles; kt++) {                                        \
        if (kt + 1 < ntiles) LOAD_STAGE((kt + 1) & 1, (kt + 1) << 5);            \
        cp_commit();                                                             \
        cp_wait<1>();                                                            \
        __syncthreads();                                                         \
        const uint32_t sb = sbase + (kt & 1) * STAGE_BYTES;                      \
        _Pragma("unroll")                                                        \
        for (int ks = 0; ks < 2; ks++) {                                         \
            uint32_t ah[4][4], al[4][4];                                         \
            _Pragma("unroll")                                                    \
            for (int mt = 0; mt < 4; mt++) {                                     \
                const uint32_t base = sb + 2 * ((wr * 64 + mt * 16) * APAD + ks * 16 + a_lm); \
                ldsm_x4(ah[mt], base + OFF_AH);                                  \
                ldsm_x4(al[mt], base + OFF_AL);                                  \
            }                                                                    \
            _Pragma("unroll")                                                    \
            for (int np = 0; np < 2; np++) {                                     \
                uint32_t bh[4], bl[4];                                           \
                const uint32_t base = sb + 2 * ((ks * 16) * BPAD + wc * 32 + np * 16 + b_lm); \
                ldsm_x4t(bh, base + OFF_BH);                                     \
                ldsm_x4t(bl, base + OFF_BL);                                     \
                _Pragma("unroll")                                                \
                for (int mt = 0; mt < 4; mt++) {                                 \
                    mma16816(acc[mt][np * 2 + 0], ah[mt], bh[0], bh[1]);         \
                    mma16816(acc[mt][np * 2 + 0], ah[mt], bl[0], bl[1]);         \
                    mma16816(acc[mt][np * 2 + 0], al[mt], bh[0], bh[1]);         \
                    mma16816(acc[mt][np * 2 + 1], ah[mt], bh[2], bh[3]);         \
                    mma16816(acc[mt][np * 2 + 1], ah[mt], bl[2], bl[3]);         \
                    mma16816(acc[mt][np * 2 + 1], al[mt], bh[2], bh[3]);         \
                }                                                                \
            }                                                                    \
        }                                                                        \
        __syncthreads();                                                         \
    }

// ---------------------------------------------------------------------------
// Generic GEMM (EPI: 0 none | 2 +bias,gelu ; OUT: 0 fp32 | 1 split)
// ---------------------------------------------------------------------------
template <int EPI, int OUT>
__global__ __launch_bounds__(256) void gemm_pipe(
    const ushort_t* __restrict__ Ah, const ushort_t* __restrict__ Al,
    const ushort_t* __restrict__ Wh, const ushort_t* __restrict__ Wl,
    const float* __restrict__ bias,
    float* __restrict__ Cf, ushort_t* __restrict__ Ch, ushort_t* __restrict__ Cl,
    int M, int K, int N)
{
    GEMM_PREAMBLE()
    const int rowBase = blockIdx.y * 128;
    const int colBase = blockIdx.x * 128;

    const ushort_t* Agh = Ah + (size_t)(rowBase + ar) * K + ac;
    const ushort_t* Agl = Al + (size_t)(rowBase + ar) * K + ac;
    const ushort_t* Wgh = Wh + (size_t)br * N + colBase + bc;
    const ushort_t* Wgl = Wl + (size_t)br * N + colBase + bc;

    GEMM_MAINLOOP()

    const int g  = lane >> 2;
    const int tq = lane & 3;
    const int rB = rowBase + wr * 64;
    const int cB = colBase + wc * 32;

#pragma unroll
    for (int mt = 0; mt < 4; mt++) {
#pragma unroll
        for (int nt = 0; nt < 4; nt++) {
            const int row = rB + mt * 16 + g;
            const int col = cB + nt * 8 + tq * 2;
            float b0 = 0.f, b1 = 0.f;
            if (EPI >= 1) { b0 = bias[col]; b1 = bias[col + 1]; }
            float v0 = acc[mt][nt][0] + b0;
            float v1 = acc[mt][nt][1] + b1;
            float v2 = acc[mt][nt][2] + b0;
            float v3 = acc[mt][nt][3] + b1;
            if (EPI == 2) {
                v0 = 0.5f * v0 * (1.0f + erff(v0 * 0.7071067811865475f));
                v1 = 0.5f * v1 * (1.0f + erff(v1 * 0.7071067811865475f));
                v2 = 0.5f * v2 * (1.0f + erff(v2 * 0.7071067811865475f));
                v3 = 0.5f * v3 * (1.0f + erff(v3 * 0.7071067811865475f));
            }
            if (OUT == 0) {
                *(float2*)&Cf[(size_t)row * N + col]       = make_float2(v0, v1);
                *(float2*)&Cf[(size_t)(row + 8) * N + col] = make_float2(v2, v3);
            } else {
                uint32_t ph, pl;
                split2(v0, v1, ph, pl);
                *(uint32_t*)&Ch[(size_t)row * N + col] = ph;
                *(uint32_t*)&Cl[(size_t)row * N + col] = pl;
                split2(v2, v3, ph, pl);
                *(uint32_t*)&Ch[(size_t)(row + 8) * N + col] = ph;
                *(uint32_t*)&Cl[(size_t)(row + 8) * N + col] = pl;
            }
        }
    }
}

// ---------------------------------------------------------------------------
// Fused QKV GEMM: one launch, grid (24, 32). blockIdx.x>>3 selects Q/K/V.
// ---------------------------------------------------------------------------
__global__ __launch_bounds__(256) void gemm_qkv(
    const ushort_t* __restrict__ Ah, const ushort_t* __restrict__ Al,
    const ushort_t* __restrict__ Wqh, const ushort_t* __restrict__ Wql,
    const ushort_t* __restrict__ Wkh, const ushort_t* __restrict__ Wkl,
    const ushort_t* __restrict__ Wvh, const ushort_t* __restrict__ Wvl,
    const float* __restrict__ bq, const float* __restrict__ bk, const float* __restrict__ bv,
    ushort_t* __restrict__ Qh, ushort_t* __restrict__ Ql,
    ushort_t* __restrict__ Kh, ushort_t* __restrict__ Kl,
    ushort_t* __restrict__ Vh, ushort_t* __restrict__ Vl)
{
    GEMM_PREAMBLE()
    const int K = DMODEL, N = DMODEL;
    const int sel = blockIdx.x >> 3;
    const int rowBase = blockIdx.y * 128;
    const int colBase = (blockIdx.x & 7) * 128;

    const ushort_t* Wh = (sel == 0) ? Wqh : (sel == 1) ? Wkh : Wvh;
    const ushort_t* Wl = (sel == 0) ? Wql : (sel == 1) ? Wkl : Wvl;
    const float* bias  = (sel == 0) ? bq  : (sel == 1) ? bk  : bv;
    ushort_t* Ch       = (sel == 0) ? Qh  : (sel == 1) ? Kh  : Vh;
    ushort_t* Cl       = (sel == 0) ? Ql  : (sel == 1) ? Kl  : Vl;
    const float scale  = (sel == 0) ? 0.125f : 1.0f;

    const ushort_t* Agh = Ah + (size_t)(rowBase + ar) * K + ac;
    const ushort_t* Agl = Al + (size_t)(rowBase + ar) * K + ac;
    const ushort_t* Wgh = Wh + (size_t)br * N + colBase + bc;
    const ushort_t* Wgl = Wl + (size_t)br * N + colBase + bc;

    GEMM_MAINLOOP()

    const int g  = lane >> 2;
    const int tq = lane & 3;
    const int rB = rowBase + wr * 64;
    const int cB = colBase + wc * 32;

#pragma unroll
    for (int mt = 0; mt < 4; mt++) {
#pragma unroll
        for (int nt = 0; nt < 4; nt++) {
            const int row = rB + mt * 16 + g;
            const int col = cB + nt * 8 + tq * 2;
            const float b0 = bias[col], b1 = bias[col + 1];
            float v0 = (acc[mt][nt][0] + b0) * scale;
            float v1 = (acc[mt][nt][1] + b1) * scale;
            float v2 = (acc[mt][nt][2] + b0) * scale;
            float v3 = (acc[mt][nt][3] + b1) * scale;
            uint32_t ph, pl;
            split2(v0, v1, ph, pl);
            *(uint32_t*)&Ch[(size_t)row * N + col] = ph;
            *(uint32_t*)&Cl[(size_t)row * N + col] = pl;
            split2(v2, v3, ph, pl);
            *(uint32_t*)&Ch[(size_t)(row + 8) * N + col] = ph;
            *(uint32_t*)&Cl[(size_t)(row + 8) * N + col] = pl;
        }
    }
}

// ---------------------------------------------------------------------------
// Tensor-core causal flash attention (R4/R8 config: static smem, single buffer).
// Grid: (S/64, H, B). Block 128 = 4 warps x 16 query rows.
// ---------------------------------------------------------------------------
#define KPAD 72

__global__ __launch_bounds__(128) void attn_tc_kernel(
    const ushort_t* __restrict__ Qh, const ushort_t* __restrict__ Ql,
    const ushort_t* __restrict__ Kh, const ushort_t* __restrict__ Kl,
    const ushort_t* __restrict__ Vh, const ushort_t* __restrict__ Vl,
    ushort_t* __restrict__ Oh, ushort_t* __restrict__ Ol)
{
    __shared__ ushort_t sKh[64 * KPAD];
    __shared__ ushort_t sKl[64 * KPAD];
    __shared__ ushort_t sVh[64 * KPAD];
    __shared__ ushort_t sVl[64 * KPAD];

    const int qb = blockIdx.x;
    const int h  = blockIdx.y;
    const int b  = blockIdx.z;
    const int t  = threadIdx.x;
    const int lane = t & 31;
    const int warp = t >> 5;
    const int q0 = qb << 6;

    const int g  = lane >> 2;
    const int tq = lane & 3;

    const int lr = t >> 1;
    const int lc = (t & 1) << 5;
    const int lm = (lane & 15) * KPAD + (lane >> 4) * 8;

    {
        const size_t gb = (size_t)(b * SEQLEN + q0 + lr) * DMODEL + h * DHEAD + lc;
#pragma unroll
        for (int u = 0; u < 4; u++) {
            *(uint4*)&sKh[lr * KPAD + lc + u * 8] = *(const uint4*)(Qh + gb + u * 8);
            *(uint4*)&sKl[lr * KPAD + lc + u * 8] = *(const uint4*)(Ql + gb + u * 8);
        }
    }
    __syncthreads();

    uint32_t qfh[4][4], qfl[4][4];
#pragma unroll
    for (int kc = 0; kc < 4; kc++) {
        const int base = (warp * 16) * KPAD + kc * 16 + lm;
        ldsm_x4(qfh[kc], smem_u32(&sKh[base]));
        ldsm_x4(qfl[kc], smem_u32(&sKl[base]));
    }
    __syncthreads();

    float m0 = -1e30f, m1 = -1e30f, l0 = 0.f, l1 = 0.f;
    float o[8][4];
#pragma unroll
    for (int j = 0; j < 8; j++)
#pragma unroll
        for (int q = 0; q < 4; q++) o[j][q] = 0.f;

    for (int jb = 0; jb <= qb; jb++) {
        const int j0 = jb << 6;
        {
            const size_t gb = (size_t)(b * SEQLEN + j0 + lr) * DMODEL + h * DHEAD + lc;
#pragma unroll
            for (int u = 0; u < 4; u++) {
                *(uint4*)&sKh[lr * KPAD + lc + u * 8] = *(const uint4*)(Kh + gb + u * 8);
                *(uint4*)&sKl[lr * KPAD + lc + u * 8] = *(const uint4*)(Kl + gb + u * 8);
                *(uint4*)&sVh[lr * KPAD + lc + u * 8] = *(const uint4*)(Vh + gb + u * 8);
                *(uint4*)&sVl[lr * KPAD + lc + u * 8] = *(const uint4*)(Vl + gb + u * 8);
            }
        }
        __syncthreads();

        float s[8][4];
#pragma unroll
        for (int j = 0; j < 8; j++)
#pragma unroll
            for (int q = 0; q < 4; q++) s[j][q] = 0.f;

#pragma unroll
        for (int kc = 0; kc < 4; kc++) {
#pragma unroll
            for (int kt = 0; kt < 4; kt++) {
                uint32_t kbh[4], kbl[4];
                const int base = (kt * 16) * KPAD + kc * 16 + lm;
                ldsm_x4(kbh, smem_u32(&sKh[base]));
                ldsm_x4(kbl, smem_u32(&sKl[base]));
                mma16816(s[kt * 2 + 0], qfh[kc], kbh[0], kbh[2]);
                mma16816(s[kt * 2 + 0], qfh[kc], kbl[0], kbl[2]);
                mma16816(s[kt * 2 + 0], qfl[kc], kbh[0], kbh[2]);
                mma16816(s[kt * 2 + 1], qfh[kc], kbh[1], kbh[3]);
                mma16816(s[kt * 2 + 1], qfh[kc], kbl[1], kbl[3]);
                mma16816(s[kt * 2 + 1], qfl[kc], kbh[1], kbh[3]);
            }
        }

        if (jb == qb) {
            const int r0 = warp * 16 + g;
            const int r1 = r0 + 8;
#pragma unroll
            for (int j = 0; j < 8; j++) {
                const int c0 = j * 8 + tq * 2;
                if (c0 > r0)     s[j][0] = -1e30f;
                if (c0 + 1 > r0) s[j][1] = -1e30f;
                if (c0 > r1)     s[j][2] = -1e30f;
                if (c0 + 1 > r1) s[j][3] = -1e30f;
            }
        }

        float rm0 = -1e30f, rm1 = -1e30f;
#pragma unroll
        for (int j = 0; j < 8; j++) {
            rm0 = fmaxf(rm0, fmaxf(s[j][0], s[j][1]));
            rm1 = fmaxf(rm1, fmaxf(s[j][2], s[j][3]));
        }
        rm0 = fmaxf(rm0, __shfl_xor_sync(0xffffffffu, rm0, 1));
        rm0 = fmaxf(rm0, __shfl_xor_sync(0xffffffffu, rm0, 2));
        rm1 = fmaxf(rm1, __shfl_xor_sync(0xffffffffu, rm1, 1));
        rm1 = fmaxf(rm1, __shfl_xor_sync(0xffffffffu, rm1, 2));
        const float nm0 = fmaxf(m0, rm0);
        const float nm1 = fmaxf(m1, rm1);

        float rs0 = 0.f, rs1 = 0.f;
#pragma unroll
        for (int j = 0; j < 8; j++) {
            s[j][0] = __expf(s[j][0] - nm0);
            s[j][1] = __expf(s[j][1] - nm0);
            s[j][2] = __expf(s[j][2] - nm1);
            s[j][3] = __expf(s[j][3] - nm1);
            rs0 += s[j][0] + s[j][1];
            rs1 += s[j][2] + s[j][3];
        }
        rs0 += __shfl_xor_sync(0xffffffffu, rs0, 1);
        rs0 += __shfl_xor_sync(0xffffffffu, rs0, 2);
        rs1 += __shfl_xor_sync(0xffffffffu, rs1, 1);
        rs1 += __shfl_xor_sync(0xffffffffu, rs1, 2);

        const float sc0 = __expf(m0 - nm0);
        const float sc1 = __expf(m1 - nm1);
        l0 = l0 * sc0 + rs0;  m0 = nm0;
        l1 = l1 * sc1 + rs1;  m1 = nm1;
#pragma unroll
        for (int j = 0; j < 8; j++) {
            o[j][0] *= sc0; o[j][1] *= sc0;
            o[j][2] *= sc1; o[j][3] *= sc1;
        }

#pragma unroll
        for (int kc = 0; kc < 4; kc++) {
            uint32_t pah[4], pal[4];
            split2(s[2 * kc + 0][0], s[2 * kc + 0][1], pah[0], pal[0]);
            split2(s[2 * kc + 0][2], s[2 * kc + 0][3], pah[1], pal[1]);
            split2(s[2 * kc + 1][0], s[2 * kc + 1][1], pah[2], pal[2]);
            split2(s[2 * kc + 1][2], s[2 * kc + 1][3], pah[3], pal[3]);
#pragma unroll
            for (int dt = 0; dt < 4; dt++) {
                uint32_t vbh[4], vbl[4];
                const int base = (kc * 16) * KPAD + dt * 16 + lm;
                ldsm_x4t(vbh, smem_u32(&sVh[base]));
                ldsm_x4t(vbl, smem_u32(&sVl[base]));
                mma16816(o[dt * 2 + 0], pah, vbh[0], vbh[1]);
                mma16816(o[dt * 2 + 0], pah, vbl[0], vbl[1]);
                mma16816(o[dt * 2 + 0], pal, vbh[0], vbh[1]);
                mma16816(o[dt * 2 + 1], pah, vbh[2], vbh[3]);
                mma16816(o[dt * 2 + 1], pah, vbl[2], vbl[3]);
                mma16816(o[dt * 2 + 1], pal, vbh[2], vbh[3]);
            }
        }
        __syncthreads();
    }

    const float inv0 = 1.0f / l0;
    const float inv1 = 1.0f / l1;
    const int row0 = q0 + warp * 16 + g;
#pragma unroll
    for (int j = 0; j < 8; j++) {
        const int col = h * DHEAD + j * 8 + tq * 2;
        uint32_t phh, pll;
        split2(o[j][0] * inv0, o[j][1] * inv0, phh, pll);
        *(uint32_t*)&Oh[(size_t)(b * SEQLEN + row0) * DMODEL + col] = phh;
        *(uint32_t*)&Ol[(size_t)(b * SEQLEN + row0) * DMODEL + col] = pll;
        split2(o[j][2] * inv1, o[j][3] * inv1, phh, pll);
        *(uint32_t*)&Oh[(size_t)(b * SEQLEN + row0 + 8) * DMODEL + col] = phh;
        *(uint32_t*)&Ol[(size_t)(b * SEQLEN + row0 + 8) * DMODEL + col] = pll;
    }
}

// ---------------------------------------------------------------------------
// LN: one block per row, float4 per thread, warp-shuffle reduction.
// ---------------------------------------------------------------------------
template <bool SPLIT>
__global__ __launch_bounds__(256) void ln_res_kernel(
    const float* __restrict__ xres, const float* __restrict__ tin,
    const float* __restrict__ gam, const float* __restrict__ bet,
    float* __restrict__ out, ushort_t* __restrict__ outh, ushort_t* __restrict__ outl)
{
    const int row = blockIdx.x;
    const int tid = threadIdx.x;
    const int lane = tid & 31;
    const int warp = tid >> 5;

    const float4 v = ((const float4*)(tin + (size_t)row * DMODEL))[tid];

    float sum = v.x + v.y + v.z + v.w;
    float sq  = v.x * v.x + v.y * v.y + v.z * v.z + v.w * v.w;
#pragma unroll
    for (int off = 16; off; off >>= 1) {
        sum += __shfl_xor_sync(0xffffffffu, sum, off);
        sq  += __shfl_xor_sync(0xffffffffu, sq,  off);
    }

    __shared__ float sS[8], sQ[8];
    __shared__ float s_mu, s_rstd;
    if (lane == 0) { sS[warp] = sum; sQ[warp] = sq; }
    __syncthreads();
    if (tid == 0) {
        float ts = 0.f, tq2 = 0.f;
#pragma unroll
        for (int w = 0; w < 8; w++) { ts += sS[w]; tq2 += sQ[w]; }
        const float mu  = ts * (1.0f / DMODEL);
        const float var = tq2 * (1.0f / DMODEL) - mu * mu;
        s_mu = mu;
        s_rstd = rsqrtf(var + 1e-5f);
    }
    __syncthreads();

    const float mu = s_mu, rstd = s_rstd;
    const float4 xr = ((const float4*)(xres + (size_t)row * DMODEL))[tid];
    const float4 gm = ((const float4*)gam)[tid];
    const float4 bt = ((const float4*)bet)[tid];

    float4 ov;
    ov.x = xr.x + (v.x - mu) * rstd * gm.x + bt.x;
    ov.y = xr.y + (v.y - mu) * rstd * gm.y + bt.y;
    ov.z = xr.z + (v.z - mu) * rstd * gm.z + bt.z;
    ov.w = xr.w + (v.w - mu) * rstd * gm.w + bt.w;

    ((float4*)(out + (size_t)row * DMODEL))[tid] = ov;
    if (SPLIT) {
        uint32_t h0, l0, h1, l1;
        split2(ov.x, ov.y, h0, l0);
        split2(ov.z, ov.w, h1, l1);
        ((uint2*)outh)[(size_t)row * 256 + tid] = make_uint2(h0, h1);
        ((uint2*)outl)[(size_t)row * 256 + tid] = make_uint2(l0, l1);
    }
}

// ---------------------------------------------------------------------------
extern "C" void kernel_launch(void* const* d_in, const int* in_sizes, int n_in,
                              void* d_out, int out_size)
{
    const float* x    = (const float*)d_in[0];
    const float* wq   = (const float*)d_in[1];
    const float* bq   = (const float*)d_in[2];
    const float* wk   = (const float*)d_in[3];
    const float* bk   = (const float*)d_in[4];
    const float* wv   = (const float*)d_in[5];
    const float* bv   = (const float*)d_in[6];
    const float* wo   = (const float*)d_in[7];
    const float* ln1g = (const float*)d_in[8];
    const float* ln1b = (const float*)d_in[9];
    const float* w1   = (const float*)d_in[10];
    const float* b1   = (const float*)d_in[11];
    const float* w2   = (const float*)d_in[12];
    const float* ln2g = (const float*)d_in[13];
    const float* ln2b = (const float*)d_in[14];
    float* out = (float*)d_out;

#define SYM(T, name, sym) T* name; { void* p_; cudaGetSymbolAddress(&p_, sym); name = (T*)p_; }
    SYM(ushort_t, xh, g_xh)   SYM(ushort_t, xl, g_xl)
    SYM(ushort_t, Qh, g_Qh)   SYM(ushort_t, Ql, g_Ql)
    SYM(ushort_t, Kh, g_Kh)   SYM(ushort_t, Kl, g_Kl)
    SYM(ushort_t, Vh, g_Vh)   SYM(ushort_t, Vl, g_Vl)
    SYM(ushort_t, ctxh, g_ctxh) SYM(ushort_t, ctxl, g_ctxl)
    SYM(ushort_t, x1h, g_x1h) SYM(ushort_t, x1l, g_x1l)
    SYM(ushort_t, hh, g_hh)   SYM(ushort_t, hl, g_hl)
    SYM(float, x1f, g_x1)     SYM(float, tmp, g_tmp)
    SYM(ushort_t, wqh, g_wqh) SYM(ushort_t, wql, g_wql)
    SYM(ushort_t, wkh, g_wkh) SYM(ushort_t, wkl, g_wkl)
    SYM(ushort_t, wvh, g_wvh) SYM(ushort_t, wvl, g_wvl)
    SYM(ushort_t, woh, g_woh) SYM(ushort_t, wol, g_wol)
    SYM(ushort_t, w1h, g_w1h) SYM(ushort_t, w1l, g_w1l)
    SYM(ushort_t, w2h, g_w2h) SYM(ushort_t, w2l, g_w2l)
#undef SYM

    static bool attr_done = false;
    if (!attr_done) {
        cudaFuncSetAttribute(gemm_pipe<0, 0>, cudaFuncAttributeMaxDynamicSharedMemorySize, GEMM_SMEM);
        cudaFuncSetAttribute(gemm_pipe<2, 1>, cudaFuncAttributeMaxDynamicSharedMemorySize, GEMM_SMEM);
        cudaFuncSetAttribute(gemm_qkv,        cudaFuncAttributeMaxDynamicSharedMemorySize, GEMM_SMEM);
        attr_done = true;
    }

    // 0) one-time splits: single merged launch (7 segments)
    {
        SplitArgs a;
        const float4* ins[7] = {(const float4*)x, (const float4*)wq, (const float4*)wk,
                                (const float4*)wv, (const float4*)wo, (const float4*)w1,
                                (const float4*)w2};
        uint2* his[7] = {(uint2*)xh, (uint2*)wqh, (uint2*)wkh, (uint2*)wvh,
                         (uint2*)woh, (uint2*)w1h, (uint2*)w2h};
        uint2* los[7] = {(uint2*)xl, (uint2*)wql, (uint2*)wkl, (uint2*)wvl,
                         (uint2*)wol, (uint2*)w1l, (uint2*)w2l};
        const int nblk[7] = {TOK * DMODEL / 1024, DMODEL * DMODEL / 1024,
                             DMODEL * DMODEL / 1024, DMODEL * DMODEL / 1024,
                             DMODEL * DMODEL / 1024, DMODEL * DHID / 1024,
                             DHID * DMODEL / 1024};
        int acc = 0;
        for (int i = 0; i < 7; i++) {
            a.in[i] = ins[i]; a.hi[i] = his[i]; a.lo[i] = los[i];
            a.start[i] = acc; acc += nblk[i];
        }
        a.start[7] = acc;
        split_all_kernel<<<acc, 256>>>(a);
    }

    // 1) fused QKV projection (Q pre-scaled by 1/8)
    gemm_qkv<<<dim3(24, 32), 256, GEMM_SMEM>>>(
        xh, xl, wqh, wql, wkh, wkl, wvh, wvl, bq, bk, bv,
        Qh, Ql, Kh, Kl, Vh, Vl);

    // 2) attention
    attn_tc_kernel<<<dim3(SEQLEN / 64, NHEADS, 2), 128>>>(Qh, Ql, Kh, Kl, Vh, Vl, ctxh, ctxl);

    // 3) Wo projection -> tmp (fp32)
    gemm_pipe<0, 0><<<dim3(8, 32), 256, GEMM_SMEM>>>(ctxh, ctxl, woh, wol, nullptr, tmp, nullptr, nullptr, TOK, DMODEL, DMODEL);

    // 4) x1 = x + LN1(tmp), also split
    ln_res_kernel<true><<<TOK, 256>>>(x, tmp, ln1g, ln1b, x1f, x1h, x1l);

    // 5) h = gelu(x1 @ w1 + b1), split out
    gemm_pipe<2, 1><<<dim3(32, 32), 256, GEMM_SMEM>>>(x1h, x1l, w1h, w1l, b1, nullptr, hh, hl, TOK, DMODEL, DHID);

    // 6) tmp = h @ w2
    gemm_pipe<0, 0><<<dim3(8, 32), 256, GEMM_SMEM>>>(hh, hl, w2h, w2l, nullptr, tmp, nullptr, nullptr, TOK, DHID, DMODEL);

    // 7) out = x1 + LN2(tmp)
    ln_res_kernel<false><<<TOK, 256>>>(x1f, tmp, ln2g, ln2b, out, nullptr, nullptr);
}

// round 13
// speedup vs baseline: 1.0865x; 1.0354x over previous
#include <cuda_runtime.h>
#include <cuda_bf16.h>
#include <math.h>
#include <stdint.h>

// Problem constants
#define TOK     4096
#define DMODEL  1024
#define DHID    4096
#define NHEADS  16
#define DHEAD   64
#define SEQLEN  2048

typedef unsigned short ushort_t;

// ---------------- Scratch (allocation-free __device__ globals) -------------
__device__ ushort_t g_xh[TOK * DMODEL],  g_xl[TOK * DMODEL];
__device__ ushort_t g_Qh[TOK * DMODEL],  g_Ql[TOK * DMODEL];
__device__ ushort_t g_Kh[TOK * DMODEL],  g_Kl[TOK * DMODEL];
__device__ ushort_t g_Vh[TOK * DMODEL],  g_Vl[TOK * DMODEL];
__device__ ushort_t g_ctxh[TOK * DMODEL], g_ctxl[TOK * DMODEL];
__device__ ushort_t g_x1h[TOK * DMODEL], g_x1l[TOK * DMODEL];
__device__ ushort_t g_hh[TOK * DHID],    g_hl[TOK * DHID];
__device__ float g_x1[TOK * DMODEL];
__device__ float g_tmp[TOK * DMODEL];
__device__ ushort_t g_wqh[DMODEL * DMODEL], g_wql[DMODEL * DMODEL];
__device__ ushort_t g_wkh[DMODEL * DMODEL], g_wkl[DMODEL * DMODEL];
__device__ ushort_t g_wvh[DMODEL * DMODEL], g_wvl[DMODEL * DMODEL];
__device__ ushort_t g_woh[DMODEL * DMODEL], g_wol[DMODEL * DMODEL];
__device__ ushort_t g_w1h[DMODEL * DHID],   g_w1l[DMODEL * DHID];
__device__ ushort_t g_w2h[DHID * DMODEL],   g_w2l[DHID * DMODEL];

// ---------------------------------------------------------------------------
// Helpers
// ---------------------------------------------------------------------------
__device__ __forceinline__ uint32_t smem_u32(const void* p) {
    return (uint32_t)__cvta_generic_to_shared(p);
}
__device__ __forceinline__ void ldsm_x4(uint32_t* r, uint32_t a) {
    asm volatile("ldmatrix.sync.aligned.m8n8.x4.shared.b16 {%0,%1,%2,%3},[%4];\n"
                 : "=r"(r[0]), "=r"(r[1]), "=r"(r[2]), "=r"(r[3]) : "r"(a));
}
__device__ __forceinline__ void ldsm_x4t(uint32_t* r, uint32_t a) {
    asm volatile("ldmatrix.sync.aligned.m8n8.x4.trans.shared.b16 {%0,%1,%2,%3},[%4];\n"
                 : "=r"(r[0]), "=r"(r[1]), "=r"(r[2]), "=r"(r[3]) : "r"(a));
}
__device__ __forceinline__ void mma16816(float* d, const uint32_t* a, uint32_t b0, uint32_t b1) {
    asm volatile("mma.sync.aligned.m16n8k16.row.col.f32.bf16.bf16.f32 "
                 "{%0,%1,%2,%3},{%4,%5,%6,%7},{%8,%9},{%0,%1,%2,%3};\n"
                 : "+f"(d[0]), "+f"(d[1]), "+f"(d[2]), "+f"(d[3])
                 : "r"(a[0]), "r"(a[1]), "r"(a[2]), "r"(a[3]), "r"(b0), "r"(b1));
}
__device__ __forceinline__ void cp16(uint32_t dst, const void* src) {
    asm volatile("cp.async.ca.shared.global [%0], [%1], 16;\n" :: "r"(dst), "l"(src));
}
__device__ __forceinline__ void cp_commit() {
    asm volatile("cp.async.commit_group;\n");
}
template <int N>
__device__ __forceinline__ void cp_wait() {
    asm volatile("cp.async.wait_group %0;\n" :: "n"(N));
}
__device__ __forceinline__ void split2(float x, float y, uint32_t& hi, uint32_t& lo) {
    __nv_bfloat16 hx = __float2bfloat16(x), hy = __float2bfloat16(y);
    float rx = x - __bfloat162float(hx), ry = y - __bfloat162float(hy);
    __nv_bfloat16 lx = __float2bfloat16(rx), ly = __float2bfloat16(ry);
    hi = (uint32_t)__bfloat16_as_ushort(hx) | ((uint32_t)__bfloat16_as_ushort(hy) << 16);
    lo = (uint32_t)__bfloat16_as_ushort(lx) | ((uint32_t)__bfloat16_as_ushort(ly) << 16);
}

// ---------------------------------------------------------------------------
// Merged split kernel: 7 tensors in one launch. Segment table by value.
// ---------------------------------------------------------------------------
struct SplitArgs {
    const float4* in[7];
    uint2* hi[7];
    uint2* lo[7];
    int start[8];    // prefix sums of block counts
};

__global__ __launch_bounds__(256) void split_all_kernel(SplitArgs a)
{
    const int blk = blockIdx.x;
    int seg = 0;
#pragma unroll
    for (int i = 1; i < 7; i++) seg += (blk >= a.start[i]);
    const int idx = (blk - a.start[seg]) * 256 + threadIdx.x;

    float4 v = a.in[seg][idx];
    uint32_t h0, l0, h1, l1;
    split2(v.x, v.y, h0, l0);
    split2(v.z, v.w, h1, l1);
    a.hi[seg][idx] = make_uint2(h0, h1);
    a.lo[seg][idx] = make_uint2(l0, l1);
}

// ---------------------------------------------------------------------------
// Shared GEMM config (R4-proven: CTA 128x128, BK=32, 2-stage, 2 CTAs/SM)
// ---------------------------------------------------------------------------
#define APAD 40
#define BPAD 136
#define OFF_AH 0
#define OFF_AL (128 * APAD * 2)
#define OFF_BH (OFF_AL + 128 * APAD * 2)
#define OFF_BL (OFF_BH + 32 * BPAD * 2)
#define STAGE_BYTES (OFF_BL + 32 * BPAD * 2)   // 37888
#define GEMM_SMEM (2 * STAGE_BYTES)            // 75776

#define GEMM_PREAMBLE()                                                          \
    extern __shared__ char smem[];                                               \
    const uint32_t sbase = smem_u32(smem);                                       \
    const int t    = threadIdx.x;                                                \
    const int lane = t & 31;                                                     \
    const int warp = t >> 5;                                                     \
    const int wr   = warp >> 2;                                                  \
    const int wc   = warp & 3;                                                   \
    const int ar = t >> 2;                                                       \
    const int ac = (t & 3) << 3;                                                 \
    const int br = t >> 3;                                                       \
    const int bc = (t & 7) << 3;                                                 \
    const uint32_t dA0 = (uint32_t)(ar * APAD + ac) * 2;                         \
    const uint32_t dA1 = (uint32_t)((ar + 64) * APAD + ac) * 2;                  \
    const uint32_t dB0 = (uint32_t)(br * BPAD + bc) * 2;                         \
    const uint32_t dB1 = (uint32_t)(br * BPAD + bc + 64) * 2;                    \
    const int a_lm = (lane & 15) * APAD + (lane >> 4) * 8;                       \
    const int b_lm = (lane & 15) * BPAD + (lane >> 4) * 8;

#define LOAD_STAGE(s, k0)                                                        \
    do {                                                                         \
        const uint32_t sb = sbase + (s) * STAGE_BYTES;                           \
        cp16(sb + OFF_AH + dA0, Agh + (k0));                                     \
        cp16(sb + OFF_AH + dA1, Agh + (size_t)64 * K + (k0));                    \
        cp16(sb + OFF_AL + dA0, Agl + (k0));                                     \
        cp16(sb + OFF_AL + dA1, Agl + (size_t)64 * K + (k0));                    \
        cp16(sb + OFF_BH + dB0, Wgh + (size_t)(k0) * N);                         \
        cp16(sb + OFF_BH + dB1, Wgh + (size_t)(k0) * N + 64);                    \
        cp16(sb + OFF_BL + dB0, Wgl + (size_t)(k0) * N);                         \
        cp16(sb + OFF_BL + dB1, Wgl + (size_t)(k0) * N + 64);                    \
    } while (0)

#define GEMM_MAINLOOP()                                                          \
    float acc[4][4][4];                                                          \
    _Pragma("unroll")                                                            \
    for (int i = 0; i < 4; i++)                                                  \
        _Pragma("unroll")                                                        \
        for (int j = 0; j < 4; j++)                                              \
            _Pragma("unroll")                                                    \
            for (int q = 0; q < 4; q++) acc[i][j][q] = 0.f;                      \
    const int ntiles = K >> 5;                                                   \
    LOAD_STAGE(0, 0);                                                            \
    cp_commit();                                                                 \
    for (int kt = 0; kt < ntiles; kt++) {                                        \
        if (kt + 1 < ntiles) LOAD_STAGE((kt + 1) & 1, (kt + 1) << 5);            \
        cp_commit();                                                             \
        cp_wait<1>();                                                            \
        __syncthreads();                                                         \
        const uint32_t sb = sbase + (kt & 1) * STAGE_BYTES;                      \
        _Pragma("unroll")                                                        \
        for (int ks = 0; ks < 2; ks++) {                                         \
            uint32_t ah[4][4], al[4][4];                                         \
            _Pragma("unroll")                                                    \
            for (int mt = 0; mt < 4; mt++) {                                     \
                const uint32_t base = sb + 2 * ((wr * 64 + mt * 16) * APAD + ks * 16 + a_lm); \
                ldsm_x4(ah[mt], base + OFF_AH);                                  \
                ldsm_x4(al[mt], base + OFF_AL);                                  \
            }                                                                    \
            _Pragma("unroll")                                                    \
            for (int np = 0; np < 2; np++) {                                     \
                uint32_t bh[4], bl[4];                                           \
                const uint32_t base = sb + 2 * ((ks * 16) * BPAD + wc * 32 + np * 16 + b_lm); \
                ldsm_x4t(bh, base + OFF_BH);                                     \
                ldsm_x4t(bl, base + OFF_BL);                                     \
                _Pragma("unroll")                                                \
                for (int mt = 0; mt < 4; mt++) {                                 \
                    mma16816(acc[mt][np * 2 + 0], ah[mt], bh[0], bh[1]);         \
                    mma16816(acc[mt][np * 2 + 0], ah[mt], bl[0], bl[1]);         \
                    mma16816(acc[mt][np * 2 + 0], al[mt], bh[0], bh[1]);         \
                    mma16816(acc[mt][np * 2 + 1], ah[mt], bh[2], bh[3]);         \
                    mma16816(acc[mt][np * 2 + 1], ah[mt], bl[2], bl[3]);         \
                    mma16816(acc[mt][np * 2 + 1], al[mt], bh[2], bh[3]);         \
                }                                                                \
            }                                                                    \
        }                                                                        \
        __syncthreads();                                                         \
    }

// ---------------------------------------------------------------------------
// Generic GEMM (EPI: 0 none | 2 +bias,gelu ; OUT: 0 fp32 | 1 split)
// ---------------------------------------------------------------------------
template <int EPI, int OUT>
__global__ __launch_bounds__(256) void gemm_pipe(
    const ushort_t* __restrict__ Ah, const ushort_t* __restrict__ Al,
    const ushort_t* __restrict__ Wh, const ushort_t* __restrict__ Wl,
    const float* __restrict__ bias,
    float* __restrict__ Cf, ushort_t* __restrict__ Ch, ushort_t* __restrict__ Cl,
    int M, int K, int N)
{
    GEMM_PREAMBLE()
    const int rowBase = blockIdx.y * 128;
    const int colBase = blockIdx.x * 128;

    const ushort_t* Agh = Ah + (size_t)(rowBase + ar) * K + ac;
    const ushort_t* Agl = Al + (size_t)(rowBase + ar) * K + ac;
    const ushort_t* Wgh = Wh + (size_t)br * N + colBase + bc;
    const ushort_t* Wgl = Wl + (size_t)br * N + colBase + bc;

    GEMM_MAINLOOP()

    const int g  = lane >> 2;
    const int tq = lane & 3;
    const int rB = rowBase + wr * 64;
    const int cB = colBase + wc * 32;

#pragma unroll
    for (int mt = 0; mt < 4; mt++) {
#pragma unroll
        for (int nt = 0; nt < 4; nt++) {
            const int row = rB + mt * 16 + g;
            const int col = cB + nt * 8 + tq * 2;
            float b0 = 0.f, b1 = 0.f;
            if (EPI >= 1) { b0 = bias[col]; b1 = bias[col + 1]; }
            float v0 = acc[mt][nt][0] + b0;
            float v1 = acc[mt][nt][1] + b1;
            float v2 = acc[mt][nt][2] + b0;
            float v3 = acc[mt][nt][3] + b1;
            if (EPI == 2) {
                v0 = 0.5f * v0 * (1.0f + erff(v0 * 0.7071067811865475f));
                v1 = 0.5f * v1 * (1.0f + erff(v1 * 0.7071067811865475f));
                v2 = 0.5f * v2 * (1.0f + erff(v2 * 0.7071067811865475f));
                v3 = 0.5f * v3 * (1.0f + erff(v3 * 0.7071067811865475f));
            }
            if (OUT == 0) {
                *(float2*)&Cf[(size_t)row * N + col]       = make_float2(v0, v1);
                *(float2*)&Cf[(size_t)(row + 8) * N + col] = make_float2(v2, v3);
            } else {
                uint32_t ph, pl;
                split2(v0, v1, ph, pl);
                *(uint32_t*)&Ch[(size_t)row * N + col] = ph;
                *(uint32_t*)&Cl[(size_t)row * N + col] = pl;
                split2(v2, v3, ph, pl);
                *(uint32_t*)&Ch[(size_t)(row + 8) * N + col] = ph;
                *(uint32_t*)&Cl[(size_t)(row + 8) * N + col] = pl;
            }
        }
    }
}

// ---------------------------------------------------------------------------
// Fused QKV GEMM: one launch, grid (24, 32). blockIdx.x>>3 selects Q/K/V.
// ---------------------------------------------------------------------------
__global__ __launch_bounds__(256) void gemm_qkv(
    const ushort_t* __restrict__ Ah, const ushort_t* __restrict__ Al,
    const ushort_t* __restrict__ Wqh, const ushort_t* __restrict__ Wql,
    const ushort_t* __restrict__ Wkh, const ushort_t* __restrict__ Wkl,
    const ushort_t* __restrict__ Wvh, const ushort_t* __restrict__ Wvl,
    const float* __restrict__ bq, const float* __restrict__ bk, const float* __restrict__ bv,
    ushort_t* __restrict__ Qh, ushort_t* __restrict__ Ql,
    ushort_t* __restrict__ Kh, ushort_t* __restrict__ Kl,
    ushort_t* __restrict__ Vh, ushort_t* __restrict__ Vl)
{
    GEMM_PREAMBLE()
    const int K = DMODEL, N = DMODEL;
    const int sel = blockIdx.x >> 3;
    const int rowBase = blockIdx.y * 128;
    const int colBase = (blockIdx.x & 7) * 128;

    const ushort_t* Wh = (sel == 0) ? Wqh : (sel == 1) ? Wkh : Wvh;
    const ushort_t* Wl = (sel == 0) ? Wql : (sel == 1) ? Wkl : Wvl;
    const float* bias  = (sel == 0) ? bq  : (sel == 1) ? bk  : bv;
    ushort_t* Ch       = (sel == 0) ? Qh  : (sel == 1) ? Kh  : Vh;
    ushort_t* Cl       = (sel == 0) ? Ql  : (sel == 1) ? Kl  : Vl;
    const float scale  = (sel == 0) ? 0.125f : 1.0f;

    const ushort_t* Agh = Ah + (size_t)(rowBase + ar) * K + ac;
    const ushort_t* Agl = Al + (size_t)(rowBase + ar) * K + ac;
    const ushort_t* Wgh = Wh + (size_t)br * N + colBase + bc;
    const ushort_t* Wgl = Wl + (size_t)br * N + colBase + bc;

    GEMM_MAINLOOP()

    const int g  = lane >> 2;
    const int tq = lane & 3;
    const int rB = rowBase + wr * 64;
    const int cB = colBase + wc * 32;

#pragma unroll
    for (int mt = 0; mt < 4; mt++) {
#pragma unroll
        for (int nt = 0; nt < 4; nt++) {
            const int row = rB + mt * 16 + g;
            const int col = cB + nt * 8 + tq * 2;
            const float b0 = bias[col], b1 = bias[col + 1];
            float v0 = (acc[mt][nt][0] + b0) * scale;
            float v1 = (acc[mt][nt][1] + b1) * scale;
            float v2 = (acc[mt][nt][2] + b0) * scale;
            float v3 = (acc[mt][nt][3] + b1) * scale;
            uint32_t ph, pl;
            split2(v0, v1, ph, pl);
            *(uint32_t*)&Ch[(size_t)row * N + col] = ph;
            *(uint32_t*)&Cl[(size_t)row * N + col] = pl;
            split2(v2, v3, ph, pl);
            *(uint32_t*)&Ch[(size_t)(row + 8) * N + col] = ph;
            *(uint32_t*)&Cl[(size_t)(row + 8) * N + col] = pl;
        }
    }
}

// ---------------------------------------------------------------------------
// Tensor-core causal flash attention with in-place K/V software pipelining.
// sK is only read during S-compute, sV only during P.V, so:
//   - V(jb) loads (cp.async) overlap S-compute on K(jb)
//   - K(jb+1) loads overlap P.V on V(jb)
// Zero extra smem, zero occupancy change vs single-buffer version.
// Grid: (S/64, H, B). Block 128 = 4 warps x 16 query rows.
// ---------------------------------------------------------------------------
#define KPAD 72

__global__ __launch_bounds__(128) void attn_tc_kernel(
    const ushort_t* __restrict__ Qh, const ushort_t* __restrict__ Ql,
    const ushort_t* __restrict__ Kh, const ushort_t* __restrict__ Kl,
    const ushort_t* __restrict__ Vh, const ushort_t* __restrict__ Vl,
    ushort_t* __restrict__ Oh, ushort_t* __restrict__ Ol)
{
    __shared__ ushort_t sKh[64 * KPAD];
    __shared__ ushort_t sKl[64 * KPAD];
    __shared__ ushort_t sVh[64 * KPAD];
    __shared__ ushort_t sVl[64 * KPAD];

    const int qb = blockIdx.x;
    const int h  = blockIdx.y;
    const int b  = blockIdx.z;
    const int t  = threadIdx.x;
    const int lane = t & 31;
    const int warp = t >> 5;
    const int q0 = qb << 6;

    const int g  = lane >> 2;
    const int tq = lane & 3;

    const int lr = t >> 1;
    const int lc = (t & 1) << 5;
    const int lm = (lane & 15) * KPAD + (lane >> 4) * 8;

    // ---- Stage Q into sK arrays, preload fragments ----
    {
        const size_t gb = (size_t)(b * SEQLEN + q0 + lr) * DMODEL + h * DHEAD + lc;
#pragma unroll
        for (int u = 0; u < 4; u++) {
            *(uint4*)&sKh[lr * KPAD + lc + u * 8] = *(const uint4*)(Qh + gb + u * 8);
            *(uint4*)&sKl[lr * KPAD + lc + u * 8] = *(const uint4*)(Ql + gb + u * 8);
        }
    }
    __syncthreads();

    uint32_t qfh[4][4], qfl[4][4];
#pragma unroll
    for (int kc = 0; kc < 4; kc++) {
        const int base = (warp * 16) * KPAD + kc * 16 + lm;
        ldsm_x4(qfh[kc], smem_u32(&sKh[base]));
        ldsm_x4(qfl[kc], smem_u32(&sKl[base]));
    }
    __syncthreads();   // all warps done reading Q staging before K(0) overwrites

    // ---- async K / V loaders (8 x cp16 per thread each) ----
    auto load_k = [&](int j0) {
        const size_t gb = (size_t)(b * SEQLEN + j0 + lr) * DMODEL + h * DHEAD + lc;
#pragma unroll
        for (int u = 0; u < 4; u++) {
            const uint32_t d = (uint32_t)(lr * KPAD + lc + u * 8) * 2;
            cp16(smem_u32(sKh) + d, Kh + gb + u * 8);
            cp16(smem_u32(sKl) + d, Kl + gb + u * 8);
        }
    };
    auto load_v = [&](int j0) {
        const size_t gb = (size_t)(b * SEQLEN + j0 + lr) * DMODEL + h * DHEAD + lc;
#pragma unroll
        for (int u = 0; u < 4; u++) {
            const uint32_t d = (uint32_t)(lr * KPAD + lc + u * 8) * 2;
            cp16(smem_u32(sVh) + d, Vh + gb + u * 8);
            cp16(smem_u32(sVl) + d, Vl + gb + u * 8);
        }
    };

    float m0 = -1e30f, m1 = -1e30f, l0 = 0.f, l1 = 0.f;
    float o[8][4];
#pragma unroll
    for (int j = 0; j < 8; j++)
#pragma unroll
        for (int q = 0; q < 4; q++) o[j][q] = 0.f;

    // prologue: K(0)
    load_k(0);
    cp_commit();
    cp_wait<0>();
    __syncthreads();

    for (int jb = 0; jb <= qb; jb++) {
        // issue V(jb) load; overlaps S-compute below
        load_v(jb << 6);
        cp_commit();

        // ---- S = Q K^T from sK ----
        float s[8][4];
#pragma unroll
        for (int j = 0; j < 8; j++)
#pragma unroll
            for (int q = 0; q < 4; q++) s[j][q] = 0.f;

#pragma unroll
        for (int kc = 0; kc < 4; kc++) {
#pragma unroll
            for (int kt = 0; kt < 4; kt++) {
                uint32_t kbh[4], kbl[4];
                const int base = (kt * 16) * KPAD + kc * 16 + lm;
                ldsm_x4(kbh, smem_u32(&sKh[base]));
                ldsm_x4(kbl, smem_u32(&sKl[base]));
                mma16816(s[kt * 2 + 0], qfh[kc], kbh[0], kbh[2]);
                mma16816(s[kt * 2 + 0], qfh[kc], kbl[0], kbl[2]);
                mma16816(s[kt * 2 + 0], qfl[kc], kbh[0], kbh[2]);
                mma16816(s[kt * 2 + 1], qfh[kc], kbh[1], kbh[3]);
                mma16816(s[kt * 2 + 1], qfh[kc], kbl[1], kbl[3]);
                mma16816(s[kt * 2 + 1], qfl[kc], kbh[1], kbh[3]);
            }
        }

        if (jb == qb) {
            const int r0 = warp * 16 + g;
            const int r1 = r0 + 8;
#pragma unroll
            for (int j = 0; j < 8; j++) {
                const int c0 = j * 8 + tq * 2;
                if (c0 > r0)     s[j][0] = -1e30f;
                if (c0 + 1 > r0) s[j][1] = -1e30f;
                if (c0 > r1)     s[j][2] = -1e30f;
                if (c0 + 1 > r1) s[j][3] = -1e30f;
            }
        }

        // ---- online softmax (still overlapping the V load) ----
        float rm0 = -1e30f, rm1 = -1e30f;
#pragma unroll
        for (int j = 0; j < 8; j++) {
            rm0 = fmaxf(rm0, fmaxf(s[j][0], s[j][1]));
            rm1 = fmaxf(rm1, fmaxf(s[j][2], s[j][3]));
        }
        rm0 = fmaxf(rm0, __shfl_xor_sync(0xffffffffu, rm0, 1));
        rm0 = fmaxf(rm0, __shfl_xor_sync(0xffffffffu, rm0, 2));
        rm1 = fmaxf(rm1, __shfl_xor_sync(0xffffffffu, rm1, 1));
        rm1 = fmaxf(rm1, __shfl_xor_sync(0xffffffffu, rm1, 2));
        const float nm0 = fmaxf(m0, rm0);
        const float nm1 = fmaxf(m1, rm1);

        float rs0 = 0.f, rs1 = 0.f;
#pragma unroll
        for (int j = 0; j < 8; j++) {
            s[j][0] = __expf(s[j][0] - nm0);
            s[j][1] = __expf(s[j][1] - nm0);
            s[j][2] = __expf(s[j][2] - nm1);
            s[j][3] = __expf(s[j][3] - nm1);
            rs0 += s[j][0] + s[j][1];
            rs1 += s[j][2] + s[j][3];
        }
        rs0 += __shfl_xor_sync(0xffffffffu, rs0, 1);
        rs0 += __shfl_xor_sync(0xffffffffu, rs0, 2);
        rs1 += __shfl_xor_sync(0xffffffffu, rs1, 1);
        rs1 += __shfl_xor_sync(0xffffffffu, rs1, 2);

        const float sc0 = __expf(m0 - nm0);
        const float sc1 = __expf(m1 - nm1);
        l0 = l0 * sc0 + rs0;  m0 = nm0;
        l1 = l1 * sc1 + rs1;  m1 = nm1;
#pragma unroll
        for (int j = 0; j < 8; j++) {
            o[j][0] *= sc0; o[j][1] *= sc0;
            o[j][2] *= sc1; o[j][3] *= sc1;
        }

        // V(jb) ready + all warps done reading sK
        cp_wait<0>();
        __syncthreads();

        // issue K(jb+1) load; overlaps P.V below (guard: last tile has no next K)
        if (jb < qb) {
            load_k((jb + 1) << 6);
            cp_commit();
        }

        // ---- O += P V from sV ----
#pragma unroll
        for (int kc = 0; kc < 4; kc++) {
            uint32_t pah[4], pal[4];
            split2(s[2 * kc + 0][0], s[2 * kc + 0][1], pah[0], pal[0]);
            split2(s[2 * kc + 0][2], s[2 * kc + 0][3], pah[1], pal[1]);
            split2(s[2 * kc + 1][0], s[2 * kc + 1][1], pah[2], pal[2]);
            split2(s[2 * kc + 1][2], s[2 * kc + 1][3], pah[3], pal[3]);
#pragma unroll
            for (int dt = 0; dt < 4; dt++) {
                uint32_t vbh[4], vbl[4];
                const int base = (kc * 16) * KPAD + dt * 16 + lm;
                ldsm_x4t(vbh, smem_u32(&sVh[base]));
                ldsm_x4t(vbl, smem_u32(&sVl[base]));
                mma16816(o[dt * 2 + 0], pah, vbh[0], vbh[1]);
                mma16816(o[dt * 2 + 0], pah, vbl[0], vbl[1]);
                mma16816(o[dt * 2 + 0], pal, vbh[0], vbh[1]);
                mma16816(o[dt * 2 + 1], pah, vbh[2], vbh[3]);
                mma16816(o[dt * 2 + 1], pah, vbl[2], vbl[3]);
                mma16816(o[dt * 2 + 1], pal, vbh[2], vbh[3]);
            }
        }

        // K(jb+1) ready + all warps done reading sV
        cp_wait<0>();
        __syncthreads();
    }

    const float inv0 = 1.0f / l0;
    const float inv1 = 1.0f / l1;
    const int row0 = q0 + warp * 16 + g;
#pragma unroll
    for (int j = 0; j < 8; j++) {
        const int col = h * DHEAD + j * 8 + tq * 2;
        uint32_t phh, pll;
        split2(o[j][0] * inv0, o[j][1] * inv0, phh, pll);
        *(uint32_t*)&Oh[(size_t)(b * SEQLEN + row0) * DMODEL + col] = phh;
        *(uint32_t*)&Ol[(size_t)(b * SEQLEN + row0) * DMODEL + col] = pll;
        split2(o[j][2] * inv1, o[j][3] * inv1, phh, pll);
        *(uint32_t*)&Oh[(size_t)(b * SEQLEN + row0 + 8) * DMODEL + col] = phh;
        *(uint32_t*)&Ol[(size_t)(b * SEQLEN + row0 + 8) * DMODEL + col] = pll;
    }
}

// ---------------------------------------------------------------------------
// LN: one block per row, float4 per thread, warp-shuffle reduction.
// ---------------------------------------------------------------------------
template <bool SPLIT>
__global__ __launch_bounds__(256) void ln_res_kernel(
    const float* __restrict__ xres, const float* __restrict__ tin,
    const float* __restrict__ gam, const float* __restrict__ bet,
    float* __restrict__ out, ushort_t* __restrict__ outh, ushort_t* __restrict__ outl)
{
    const int row = blockIdx.x;
    const int tid = threadIdx.x;
    const int lane = tid & 31;
    const int warp = tid >> 5;

    const float4 v = ((const float4*)(tin + (size_t)row * DMODEL))[tid];

    float sum = v.x + v.y + v.z + v.w;
    float sq  = v.x * v.x + v.y * v.y + v.z * v.z + v.w * v.w;
#pragma unroll
    for (int off = 16; off; off >>= 1) {
        sum += __shfl_xor_sync(0xffffffffu, sum, off);
        sq  += __shfl_xor_sync(0xffffffffu, sq,  off);
    }

    __shared__ float sS[8], sQ[8];
    __shared__ float s_mu, s_rstd;
    if (lane == 0) { sS[warp] = sum; sQ[warp] = sq; }
    __syncthreads();
    if (tid == 0) {
        float ts = 0.f, tq2 = 0.f;
#pragma unroll
        for (int w = 0; w < 8; w++) { ts += sS[w]; tq2 += sQ[w]; }
        const float mu  = ts * (1.0f / DMODEL);
        const float var = tq2 * (1.0f / DMODEL) - mu * mu;
        s_mu = mu;
        s_rstd = rsqrtf(var + 1e-5f);
    }
    __syncthreads();

    const float mu = s_mu, rstd = s_rstd;
    const float4 xr = ((const float4*)(xres + (size_t)row * DMODEL))[tid];
    const float4 gm = ((const float4*)gam)[tid];
    const float4 bt = ((const float4*)bet)[tid];

    float4 ov;
    ov.x = xr.x + (v.x - mu) * rstd * gm.x + bt.x;
    ov.y = xr.y + (v.y - mu) * rstd * gm.y + bt.y;
    ov.z = xr.z + (v.z - mu) * rstd * gm.z + bt.z;
    ov.w = xr.w + (v.w - mu) * rstd * gm.w + bt.w;

    ((float4*)(out + (size_t)row * DMODEL))[tid] = ov;
    if (SPLIT) {
        uint32_t h0, l0, h1, l1;
        split2(ov.x, ov.y, h0, l0);
        split2(ov.z, ov.w, h1, l1);
        ((uint2*)outh)[(size_t)row * 256 + tid] = make_uint2(h0, h1);
        ((uint2*)outl)[(size_t)row * 256 + tid] = make_uint2(l0, l1);
    }
}

// ---------------------------------------------------------------------------
extern "C" void kernel_launch(void* const* d_in, const int* in_sizes, int n_in,
                              void* d_out, int out_size)
{
    const float* x    = (const float*)d_in[0];
    const float* wq   = (const float*)d_in[1];
    const float* bq   = (const float*)d_in[2];
    const float* wk   = (const float*)d_in[3];
    const float* bk   = (const float*)d_in[4];
    const float* wv   = (const float*)d_in[5];
    const float* bv   = (const float*)d_in[6];
    const float* wo   = (const float*)d_in[7];
    const float* ln1g = (const float*)d_in[8];
    const float* ln1b = (const float*)d_in[9];
    const float* w1   = (const float*)d_in[10];
    const float* b1   = (const float*)d_in[11];
    const float* w2   = (const float*)d_in[12];
    const float* ln2g = (const float*)d_in[13];
    const float* ln2b = (const float*)d_in[14];
    float* out = (float*)d_out;

#define SYM(T, name, sym) T* name; { void* p_; cudaGetSymbolAddress(&p_, sym); name = (T*)p_; }
    SYM(ushort_t, xh, g_xh)   SYM(ushort_t, xl, g_xl)
    SYM(ushort_t, Qh, g_Qh)   SYM(ushort_t, Ql, g_Ql)
    SYM(ushort_t, Kh, g_Kh)   SYM(ushort_t, Kl, g_Kl)
    SYM(ushort_t, Vh, g_Vh)   SYM(ushort_t, Vl, g_Vl)
    SYM(ushort_t, ctxh, g_ctxh) SYM(ushort_t, ctxl, g_ctxl)
    SYM(ushort_t, x1h, g_x1h) SYM(ushort_t, x1l, g_x1l)
    SYM(ushort_t, hh, g_hh)   SYM(ushort_t, hl, g_hl)
    SYM(float, x1f, g_x1)     SYM(float, tmp, g_tmp)
    SYM(ushort_t, wqh, g_wqh) SYM(ushort_t, wql, g_wql)
    SYM(ushort_t, wkh, g_wkh) SYM(ushort_t, wkl, g_wkl)
    SYM(ushort_t, wvh, g_wvh) SYM(ushort_t, wvl, g_wvl)
    SYM(ushort_t, woh, g_woh) SYM(ushort_t, wol, g_wol)
    SYM(ushort_t, w1h, g_w1h) SYM(ushort_t, w1l, g_w1l)
    SYM(ushort_t, w2h, g_w2h) SYM(ushort_t, w2l, g_w2l)
#undef SYM

    static bool attr_done = false;
    if (!attr_done) {
        cudaFuncSetAttribute(gemm_pipe<0, 0>, cudaFuncAttributeMaxDynamicSharedMemorySize, GEMM_SMEM);
        cudaFuncSetAttribute(gemm_pipe<2, 1>, cudaFuncAttributeMaxDynamicSharedMemorySize, GEMM_SMEM);
        cudaFuncSetAttribute(gemm_qkv,        cudaFuncAttributeMaxDynamicSharedMemorySize, GEMM_SMEM);
        attr_done = true;
    }

    // 0) one-time splits: single merged launch (7 segments)
    {
        SplitArgs a;
        const float4* ins[7] = {(const float4*)x, (const float4*)wq, (const float4*)wk,
                                (const float4*)wv, (const float4*)wo, (const float4*)w1,
                                (const float4*)w2};
        uint2* his[7] = {(uint2*)xh, (uint2*)wqh, (uint2*)wkh, (uint2*)wvh,
                         (uint2*)woh, (uint2*)w1h, (uint2*)w2h};
        uint2* los[7] = {(uint2*)xl, (uint2*)wql, (uint2*)wkl, (uint2*)wvl,
                         (uint2*)wol, (uint2*)w1l, (uint2*)w2l};
        const int nblk[7] = {TOK * DMODEL / 1024, DMODEL * DMODEL / 1024,
                             DMODEL * DMODEL / 1024, DMODEL * DMODEL / 1024,
                             DMODEL * DMODEL / 1024, DMODEL * DHID / 1024,
                             DHID * DMODEL / 1024};
        int acc = 0;
        for (int i = 0; i < 7; i++) {
            a.in[i] = ins[i]; a.hi[i] = his[i]; a.lo[i] = los[i];
            a.start[i] = acc; acc += nblk[i];
        }
        a.start[7] = acc;
        split_all_kernel<<<acc, 256>>>(a);
    }

    // 1) fused QKV projection (Q pre-scaled by 1/8)
    gemm_qkv<<<dim3(24, 32), 256, GEMM_SMEM>>>(
        xh, xl, wqh, wql, wkh, wkl, wvh, wvl, bq, bk, bv,
        Qh, Ql, Kh, Kl, Vh, Vl);

    // 2) attention (in-place K/V pipelined)
    attn_tc_kernel<<<dim3(SEQLEN / 64, NHEADS, 2), 128>>>(Qh, Ql, Kh, Kl, Vh, Vl, ctxh, ctxl);

    // 3) Wo projection -> tmp (fp32)
    gemm_pipe<0, 0><<<dim3(8, 32), 256, GEMM_SMEM>>>(ctxh, ctxl, woh, wol, nullptr, tmp, nullptr, nullptr, TOK, DMODEL, DMODEL);

    // 4) x1 = x + LN1(tmp), also split
    ln_res_kernel<true><<<TOK, 256>>>(x, tmp, ln1g, ln1b, x1f, x1h, x1l);

    // 5) h = gelu(x1 @ w1 + b1), split out
    gemm_pipe<2, 1><<<dim3(32, 32), 256, GEMM_SMEM>>>(x1h, x1l, w1h, w1l, b1, nullptr, hh, hl, TOK, DMODEL, DHID);

    // 6) tmp = h @ w2
    gemm_pipe<0, 0><<<dim3(8, 32), 256, GEMM_SMEM>>>(hh, hl, w2h, w2l, nullptr, tmp, nullptr, nullptr, TOK, DHID, DMODEL);

    // 7) out = x1 + LN2(tmp)
    ln_res_kernel<false><<<TOK, 256>>>(x1f, tmp, ln2g, ln2b, out, nullptr, nullptr);
}